// round 5
// baseline (speedup 1.0000x reference)
#include <cuda_runtime.h>
#include <math.h>

#define N_NODES 50000
#define N_EDGESC 400000
#define H 128
#define NT 2
#define FEAT 4

typedef unsigned long long u64;

// ---------------- packed f32x2 helpers (Blackwell FFMA2 path) ----------------
__device__ __forceinline__ u64 pack_dup(float a) {
    u64 r; unsigned int ai = __float_as_uint(a);
    asm("mov.b64 %0, {%1, %1};" : "=l"(r) : "r"(ai));
    return r;
}
__device__ __forceinline__ void ffma2(u64& d, u64 a, u64 b) {
    asm("fma.rn.f32x2 %0, %1, %2, %3;" : "=l"(d) : "l"(a), "l"(b), "l"(d));
}
__device__ __forceinline__ float2 unpack2(u64 v) {
    unsigned int lo, hi;
    asm("mov.b64 {%0, %1}, %2;" : "=r"(lo), "=r"(hi) : "l"(v));
    return make_float2(__uint_as_float(lo), __uint_as_float(hi));
}
__device__ __forceinline__ void red4(float* p, float a, float b, float c, float d) {
    asm volatile("red.global.add.v4.f32 [%0], {%1, %2, %3, %4};"
                 :: "l"(p), "f"(a), "f"(b), "f"(c), "f"(d) : "memory");
}

// ---------------- device scratch ----------------
__device__ float g_h[N_NODES * H];
__device__ float g_agg[N_NODES * H];
__device__ float g_gi[N_NODES * 3 * H];
__device__ float g_gh[N_NODES * 3 * H];
__device__ int   g_perm[N_EDGESC];
__device__ int   g_cnt[2];
__device__ int   g_cursor[2];

__device__ __forceinline__ float sigm(float v) { return 1.0f / (1.0f + expf(-v)); }

// ---------------- edge partition by type ----------------
__global__ void k_zero_cnt() {
    if (threadIdx.x < 2) g_cnt[threadIdx.x] = 0;
}

__global__ void k_count(const int* __restrict__ et) {
    __shared__ int lc[2];
    if (threadIdx.x < 2) lc[threadIdx.x] = 0;
    __syncthreads();
    int e = blockIdx.x * blockDim.x + threadIdx.x;
    if (e < N_EDGESC) atomicAdd(&lc[et[e]], 1);
    __syncthreads();
    if (threadIdx.x < 2) atomicAdd(&g_cnt[threadIdx.x], lc[threadIdx.x]);
}

__global__ void k_seed() {
    g_cursor[0] = 0;
    g_cursor[1] = g_cnt[0];
}

__global__ void k_scatter(const int* __restrict__ et) {
    __shared__ int lc[2];
    __shared__ int base[2];
    if (threadIdx.x < 2) lc[threadIdx.x] = 0;
    __syncthreads();
    int e = blockIdx.x * blockDim.x + threadIdx.x;
    int t = 0, rank = 0;
    bool valid = (e < N_EDGESC);
    if (valid) {
        t = et[e];
        rank = atomicAdd(&lc[t], 1);
    }
    __syncthreads();
    if (threadIdx.x < 2) base[threadIdx.x] = atomicAdd(&g_cursor[threadIdx.x], lc[threadIdx.x]);
    __syncthreads();
    if (valid) g_perm[base[t] + rank] = e;
}

// ---------------- h = relu(x @ W_in + b_in) ----------------
__global__ void k_init(const float* __restrict__ x, const float* __restrict__ Win,
                       const float* __restrict__ bin) {
    __shared__ float sW[FEAT * H];
    __shared__ float sb[H];
    for (int i = threadIdx.x; i < FEAT * H; i += blockDim.x) sW[i] = Win[i];
    if (threadIdx.x < H) sb[threadIdx.x] = bin[threadIdx.x];
    __syncthreads();
    int idx = blockIdx.x * blockDim.x + threadIdx.x;
    if (idx >= N_NODES * H) return;
    int n = idx >> 7, c = idx & 127;
    float4 xr = ((const float4*)x)[n];
    float v = sb[c] + xr.x * sW[c] + xr.y * sW[H + c] + xr.z * sW[2 * H + c] + xr.w * sW[3 * H + c];
    g_h[idx] = fmaxf(v, 0.0f);
}

__global__ void k_zero_agg() {
    int i = blockIdx.x * blockDim.x + threadIdx.x;
    if (i < N_NODES * H) g_agg[i] = 0.0f;
}

// ---------------- edge MLP + scatter-add (f32x2 mainloop) ----------------
__global__ __launch_bounds__(256, 2)
void k_edge_mlp(const int* __restrict__ edge_index,
                const float* __restrict__ W1, const float* __restrict__ b1,
                const float* __restrict__ W2, const float* __restrict__ b2, int l) {
    extern __shared__ float smem[];
    float* sA = smem;                  // 64*256
    float* sW = smem + 64 * 256;       // 32*128
    int* sSrc = (int*)(sW + 32 * 128); // 64
    int* sDst = sSrc + 64;             // 64

    int cnt0 = g_cnt[0];
    int nb0 = (cnt0 + 63) >> 6;
    int type, start, cnt, permBase;
    if ((int)blockIdx.x < nb0) {
        type = 0; start = blockIdx.x * 64; cnt = cnt0; permBase = 0;
    } else {
        type = 1; start = ((int)blockIdx.x - nb0) * 64;
        cnt = N_EDGESC - cnt0; permBase = cnt0;
        if (start >= cnt) return;
    }

    if (threadIdx.x < 64) {
        int g = start + threadIdx.x;
        int s = -1, d = -1;
        if (g < cnt) {
            int e = g_perm[permBase + g];
            s = edge_index[e];
            d = edge_index[N_EDGESC + e];
        }
        sSrc[threadIdx.x] = s;
        sDst[threadIdx.x] = d;
    }
    __syncthreads();

    // gather cat = [h[src], h[dst]] rows
    for (int t = threadIdx.x; t < 64 * 64; t += 256) {
        int r = t >> 6;
        int c4 = t & 63;
        int node = (c4 < 32) ? sSrc[r] : sDst[r];
        int cc = (c4 < 32) ? c4 : (c4 - 32);
        float4 v = make_float4(0.f, 0.f, 0.f, 0.f);
        if (node >= 0) v = ((const float4*)(g_h + (size_t)node * H))[cc];
        ((float4*)sA)[t] = v;
    }

    const float* W1t = W1 + (size_t)(l * NT + type) * (2 * H * H);
    const float* b1t = b1 + (l * NT + type) * H;
    const float* W2t = W2 + (size_t)(l * NT + type) * (H * H);
    const float* b2t = b2 + (l * NT + type) * H;

    int ty = threadIdx.x >> 4, tx = threadIdx.x & 15;
    const ulonglong2* sW8 = (const ulonglong2*)sW;

    // acc[i][jp]: jp pairs → cols (tx*4+2jp, tx*4+2jp+1) for jp<2, (+64) for jp>=2
    u64 acc[4][4];
#pragma unroll
    for (int i = 0; i < 4; ++i)
#pragma unroll
        for (int j = 0; j < 4; ++j) acc[i][j] = 0ull;

    // GEMM1: [64x256] @ [256x128]
    for (int kc = 0; kc < 8; ++kc) {
        __syncthreads();
        for (int t = threadIdx.x; t < 32 * 32; t += 256) {
            int wr = t >> 5;
            ((float4*)sW)[t] = *(const float4*)(W1t + (kc * 32 + wr) * H + (t & 31) * 4);
        }
        __syncthreads();
#pragma unroll
        for (int k = 0; k < 32; ++k) {
            ulonglong2 bA = sW8[k * 32 + tx];
            ulonglong2 bB = sW8[k * 32 + 16 + tx];
#pragma unroll
            for (int i = 0; i < 4; ++i) {
                u64 ap = pack_dup(sA[(ty + 16 * i) * 256 + kc * 32 + k]);
                ffma2(acc[i][0], ap, bA.x);
                ffma2(acc[i][1], ap, bA.y);
                ffma2(acc[i][2], ap, bB.x);
                ffma2(acc[i][3], ap, bB.y);
            }
        }
    }

    // hidden = relu(acc + b1) -> sC (reuse sA)
    float4 bA1 = *(const float4*)(b1t + tx * 4);
    float4 bB1 = *(const float4*)(b1t + 64 + tx * 4);
    __syncthreads();
    float* sC = sA;
#pragma unroll
    for (int i = 0; i < 4; ++i) {
        float2 p0 = unpack2(acc[i][0]), p1 = unpack2(acc[i][1]);
        float2 p2 = unpack2(acc[i][2]), p3 = unpack2(acc[i][3]);
        float4 v0, v1;
        v0.x = fmaxf(p0.x + bA1.x, 0.f); v0.y = fmaxf(p0.y + bA1.y, 0.f);
        v0.z = fmaxf(p1.x + bA1.z, 0.f); v0.w = fmaxf(p1.y + bA1.w, 0.f);
        v1.x = fmaxf(p2.x + bB1.x, 0.f); v1.y = fmaxf(p2.y + bB1.y, 0.f);
        v1.z = fmaxf(p3.x + bB1.z, 0.f); v1.w = fmaxf(p3.y + bB1.w, 0.f);
        int row = ty + 16 * i;
        ((float4*)sC)[(row * 128 + tx * 4) >> 2] = v0;
        ((float4*)sC)[(row * 128 + 64 + tx * 4) >> 2] = v1;
    }

    // GEMM2: [64x128] @ [128x128]
    u64 acc2[4][4];
#pragma unroll
    for (int i = 0; i < 4; ++i)
#pragma unroll
        for (int j = 0; j < 4; ++j) acc2[i][j] = 0ull;

    for (int kc = 0; kc < 4; ++kc) {
        __syncthreads();
        for (int t = threadIdx.x; t < 32 * 32; t += 256) {
            int wr = t >> 5;
            ((float4*)sW)[t] = *(const float4*)(W2t + (kc * 32 + wr) * H + (t & 31) * 4);
        }
        __syncthreads();
#pragma unroll
        for (int k = 0; k < 32; ++k) {
            ulonglong2 bA = sW8[k * 32 + tx];
            ulonglong2 bB = sW8[k * 32 + 16 + tx];
#pragma unroll
            for (int i = 0; i < 4; ++i) {
                u64 ap = pack_dup(sC[(ty + 16 * i) * 128 + kc * 32 + k]);
                ffma2(acc2[i][0], ap, bA.x);
                ffma2(acc2[i][1], ap, bA.y);
                ffma2(acc2[i][2], ap, bB.x);
                ffma2(acc2[i][3], ap, bB.y);
            }
        }
    }

    // epilogue: msgs = acc2 + b2, vectorized scatter-add into agg[dst]
    float4 bA2 = *(const float4*)(b2t + tx * 4);
    float4 bB2 = *(const float4*)(b2t + 64 + tx * 4);
#pragma unroll
    for (int i = 0; i < 4; ++i) {
        int d = sDst[ty + 16 * i];
        if (d < 0) continue;
        float* aggp = g_agg + (size_t)d * H;
        float2 p0 = unpack2(acc2[i][0]), p1 = unpack2(acc2[i][1]);
        float2 p2 = unpack2(acc2[i][2]), p3 = unpack2(acc2[i][3]);
        red4(aggp + tx * 4,
             p0.x + bA2.x, p0.y + bA2.y, p1.x + bA2.z, p1.y + bA2.w);
        red4(aggp + 64 + tx * 4,
             p2.x + bB2.x, p2.y + bB2.y, p3.x + bB2.z, p3.y + bB2.w);
    }
}

// ---------------- GRU GEMMs (f32x2 mainloop) ----------------
__global__ __launch_bounds__(256)
void k_gru_gemm(const float* __restrict__ Wih, const float* __restrict__ bih,
                const float* __restrict__ Whh, const float* __restrict__ bhh, int l) {
    extern __shared__ float smem[];
    float* sA = smem;            // 64*128
    float* sW = smem + 64 * H;   // 32*128

    const float* A; const float* W; const float* b; float* C;
    if (blockIdx.z == 0) { A = g_agg; W = Wih + (size_t)l * H * 3 * H; b = bih + l * 3 * H; C = g_gi; }
    else                 { A = g_h;   W = Whh + (size_t)l * H * 3 * H; b = bhh + l * 3 * H; C = g_gh; }

    int m0 = blockIdx.x * 64;
    int c0 = blockIdx.y * 128;

    for (int t = threadIdx.x; t < 64 * 32; t += 256) {
        int r = t >> 5;
        int c4 = t & 31;
        int m = m0 + r;
        float4 v = make_float4(0.f, 0.f, 0.f, 0.f);
        if (m < N_NODES) v = ((const float4*)(A + (size_t)m * H))[c4];
        ((float4*)sA)[t] = v;
    }

    int ty = threadIdx.x >> 4, tx = threadIdx.x & 15;
    const ulonglong2* sW8 = (const ulonglong2*)sW;
    u64 acc[4][4];
#pragma unroll
    for (int i = 0; i < 4; ++i)
#pragma unroll
        for (int j = 0; j < 4; ++j) acc[i][j] = 0ull;

    for (int kc = 0; kc < 4; ++kc) {
        __syncthreads();
        for (int t = threadIdx.x; t < 32 * 32; t += 256) {
            int wr = t >> 5;
            ((float4*)sW)[t] = *(const float4*)(W + (kc * 32 + wr) * (3 * H) + c0 + (t & 31) * 4);
        }
        __syncthreads();
#pragma unroll
        for (int k = 0; k < 32; ++k) {
            ulonglong2 bA = sW8[k * 32 + tx];
            ulonglong2 bB = sW8[k * 32 + 16 + tx];
#pragma unroll
            for (int i = 0; i < 4; ++i) {
                u64 ap = pack_dup(sA[(ty + 16 * i) * H + kc * 32 + k]);
                ffma2(acc[i][0], ap, bA.x);
                ffma2(acc[i][1], ap, bA.y);
                ffma2(acc[i][2], ap, bB.x);
                ffma2(acc[i][3], ap, bB.y);
            }
        }
    }

    float4 bv0 = *(const float4*)(b + c0 + tx * 4);
    float4 bv1 = *(const float4*)(b + c0 + 64 + tx * 4);
#pragma unroll
    for (int i = 0; i < 4; ++i) {
        int m = m0 + ty + 16 * i;
        if (m >= N_NODES) continue;
        float2 p0 = unpack2(acc[i][0]), p1 = unpack2(acc[i][1]);
        float2 p2 = unpack2(acc[i][2]), p3 = unpack2(acc[i][3]);
        float4 o0 = make_float4(p0.x + bv0.x, p0.y + bv0.y, p1.x + bv0.z, p1.y + bv0.w);
        float4 o1 = make_float4(p2.x + bv1.x, p2.y + bv1.y, p3.x + bv1.z, p3.y + bv1.w);
        *(float4*)(C + (size_t)m * 384 + c0 + tx * 4) = o0;
        *(float4*)(C + (size_t)m * 384 + c0 + 64 + tx * 4) = o1;
    }
}

__global__ void k_gru_combine() {
    int idx = blockIdx.x * blockDim.x + threadIdx.x;
    if (idx >= N_NODES * H) return;
    int n = idx >> 7, c = idx & 127;
    const float* gi = g_gi + (size_t)n * 384;
    const float* gh = g_gh + (size_t)n * 384;
    float r = sigm(gi[c] + gh[c]);
    float z = sigm(gi[128 + c] + gh[128 + c]);
    float nn = tanhf(gi[256 + c] + r * gh[256 + c]);
    g_h[idx] = (1.0f - z) * nn + z * g_h[idx];
}

// ---------------- readout ----------------
__global__ __launch_bounds__(256)
void k_readout(const float* __restrict__ Wr1, const float* __restrict__ br1,
               const float* __restrict__ Wr2, const float* __restrict__ br2,
               float* __restrict__ out, int nd) {
    extern __shared__ float smem[];
    float* sW1 = smem;              // 128*128
    float* sb1 = sW1 + H * H;       // 128
    float* sW2 = sb1 + H;           // 128
    float* sHrow = sW2 + H;         // 8 * 128

    for (int t = threadIdx.x; t < (H * H) / 4; t += blockDim.x)
        ((float4*)sW1)[t] = ((const float4*)Wr1)[t];
    if (threadIdx.x < H) {
        sb1[threadIdx.x] = br1[threadIdx.x];
        sW2[threadIdx.x] = Wr2[threadIdx.x];
    }
    __syncthreads();

    int w = threadIdx.x >> 5, lane = threadIdx.x & 31;
    float* myrow = sHrow + w * H;
    float b2v = br2[0];

    for (int n = blockIdx.x * 8 + w; n < nd; n += gridDim.x * 8) {
        ((float4*)myrow)[lane] = ((const float4*)(g_h + (size_t)n * H))[lane];
        __syncwarp();
        float hid0 = 0.f, hid1 = 0.f, hid2 = 0.f, hid3 = 0.f;
#pragma unroll 4
        for (int k = 0; k < H; ++k) {
            float a = myrow[k];
            float4 wv = ((const float4*)sW1)[k * 32 + lane];
            hid0 += a * wv.x; hid1 += a * wv.y; hid2 += a * wv.z; hid3 += a * wv.w;
        }
        float4 w2 = ((const float4*)sW2)[lane];
        float p = fmaxf(hid0 + sb1[lane * 4 + 0], 0.f) * w2.x
                + fmaxf(hid1 + sb1[lane * 4 + 1], 0.f) * w2.y
                + fmaxf(hid2 + sb1[lane * 4 + 2], 0.f) * w2.z
                + fmaxf(hid3 + sb1[lane * 4 + 3], 0.f) * w2.w;
#pragma unroll
        for (int o = 16; o > 0; o >>= 1) p += __shfl_down_sync(0xffffffffu, p, o);
        if (lane == 0) out[n] = p + b2v;
        __syncwarp();
    }
}

// ---------------- launch ----------------
extern "C" void kernel_launch(void* const* d_in, const int* in_sizes, int n_in,
                              void* d_out, int out_size) {
    int base = (n_in >= 18) ? 4 : 3;
    const float* x          = (const float*)d_in[0];
    const int*   edge_index = (const int*)d_in[1];
    const int*   edge_type  = (const int*)d_in[2];
    const float* W_in = (const float*)d_in[base + 0];
    const float* b_in = (const float*)d_in[base + 1];
    const float* W1   = (const float*)d_in[base + 2];
    const float* b1   = (const float*)d_in[base + 3];
    const float* W2   = (const float*)d_in[base + 4];
    const float* b2   = (const float*)d_in[base + 5];
    const float* W_ih = (const float*)d_in[base + 6];
    const float* b_ih = (const float*)d_in[base + 7];
    const float* W_hh = (const float*)d_in[base + 8];
    const float* b_hh = (const float*)d_in[base + 9];
    const float* Wr1  = (const float*)d_in[base + 10];
    const float* br1  = (const float*)d_in[base + 11];
    const float* Wr2  = (const float*)d_in[base + 12];
    const float* br2  = (const float*)d_in[base + 13];
    float* out = (float*)d_out;

    const int EDGE_SMEM = (64 * 256 + 32 * 128) * 4 + 2 * 64 * 4;
    const int GRU_SMEM  = (64 * 128 + 32 * 128) * 4;
    const int READ_SMEM = (128 * 128 + 128 + 128 + 8 * 128) * 4;
    cudaFuncSetAttribute(k_edge_mlp, cudaFuncAttributeMaxDynamicSharedMemorySize, EDGE_SMEM);
    cudaFuncSetAttribute(k_gru_gemm, cudaFuncAttributeMaxDynamicSharedMemorySize, GRU_SMEM);
    cudaFuncSetAttribute(k_readout,  cudaFuncAttributeMaxDynamicSharedMemorySize, READ_SMEM);

    k_zero_cnt<<<1, 32>>>();
    k_count<<<(N_EDGESC + 255) / 256, 256>>>(edge_type);
    k_seed<<<1, 1>>>();
    k_scatter<<<(N_EDGESC + 255) / 256, 256>>>(edge_type);

    k_init<<<(N_NODES * H + 255) / 256, 256>>>(x, W_in, b_in);

    const int NEL = N_NODES * H;
    for (int l = 0; l < 3; ++l) {
        k_zero_agg<<<(NEL + 255) / 256, 256>>>();
        k_edge_mlp<<<N_EDGESC / 64 + 1, 256, EDGE_SMEM>>>(edge_index, W1, b1, W2, b2, l);
        dim3 gg((N_NODES + 63) / 64, 3, 2);
        k_gru_gemm<<<gg, 256, GRU_SMEM>>>(W_ih, b_ih, W_hh, b_hh, l);
        k_gru_combine<<<(NEL + 255) / 256, 256>>>();
    }

    k_readout<<<625, 256, READ_SMEM>>>(Wr1, br1, Wr2, br2, out, out_size);
}

// round 9
// speedup vs baseline: 1.2967x; 1.2967x over previous
#include <cuda_runtime.h>
#include <math.h>
#include <stdint.h>

#define N_NODES 50000
#define N_EDGESC 400000
#define H 128
#define NT 2
#define FEAT 4
#define TILE_E 128

// ---------------- device scratch (no runtime allocation) ----------------
__device__ float g_h[N_NODES * H];
__device__ float g_agg[N_NODES * H];
__device__ float g_gi[N_NODES * 3 * H];
__device__ float g_gh[N_NODES * 3 * H];
__device__ int   g_perm[N_EDGESC];
__device__ int   g_cnt[2];
__device__ int   g_cursor[2];
// transposed + tf32-split weights: [lt][n][k], values already tf32-rounded
__device__ float g_W1T_hi[6 * 256 * 128];
__device__ float g_W1T_lo[6 * 256 * 128];
__device__ float g_W2T_hi[6 * 128 * 128];
__device__ float g_W2T_lo[6 * 128 * 128];

__device__ __forceinline__ float sigm(float v) { return 1.0f / (1.0f + expf(-v)); }

__device__ __forceinline__ uint32_t tf32_bits(float x) {
    uint32_t u; asm("cvt.rna.tf32.f32 %0, %1;" : "=r"(u) : "f"(x));
    return u;
}
__device__ __forceinline__ float tf32_rna(float x) {
    return __uint_as_float(tf32_bits(x));
}
// split v -> hi (tf32), lo (tf32 of remainder), as raw bits for mma
__device__ __forceinline__ void split_bits(float v, uint32_t& hi, uint32_t& lo) {
    hi = tf32_bits(v);
    lo = tf32_bits(v - __uint_as_float(hi));
}

__device__ __forceinline__ void mma_tf32(float* c, uint32_t a0, uint32_t a1, uint32_t a2,
                                         uint32_t a3, uint32_t b0, uint32_t b1) {
    asm volatile(
        "mma.sync.aligned.m16n8k8.row.col.f32.tf32.tf32.f32 "
        "{%0,%1,%2,%3}, {%4,%5,%6,%7}, {%8,%9}, {%0,%1,%2,%3};"
        : "+f"(c[0]), "+f"(c[1]), "+f"(c[2]), "+f"(c[3])
        : "r"(a0), "r"(a1), "r"(a2), "r"(a3), "r"(b0), "r"(b1));
}

__device__ __forceinline__ void red2(float* p, float a, float b) {
    asm volatile("red.global.add.v2.f32 [%0], {%1, %2};" :: "l"(p), "f"(a), "f"(b) : "memory");
}

// ---------------- edge partition by type ----------------
__global__ void k_zero_cnt() { if (threadIdx.x < 2) g_cnt[threadIdx.x] = 0; }

__global__ void k_count(const int* __restrict__ et) {
    __shared__ int lc[2];
    if (threadIdx.x < 2) lc[threadIdx.x] = 0;
    __syncthreads();
    int e = blockIdx.x * blockDim.x + threadIdx.x;
    if (e < N_EDGESC) atomicAdd(&lc[et[e]], 1);
    __syncthreads();
    if (threadIdx.x < 2) atomicAdd(&g_cnt[threadIdx.x], lc[threadIdx.x]);
}

__global__ void k_seed() { g_cursor[0] = 0; g_cursor[1] = g_cnt[0]; }

__global__ void k_scatter(const int* __restrict__ et) {
    __shared__ int lc[2];
    __shared__ int base[2];
    if (threadIdx.x < 2) lc[threadIdx.x] = 0;
    __syncthreads();
    int e = blockIdx.x * blockDim.x + threadIdx.x;
    int t = 0, rank = 0;
    bool valid = (e < N_EDGESC);
    if (valid) { t = et[e]; rank = atomicAdd(&lc[t], 1); }
    __syncthreads();
    if (threadIdx.x < 2) base[threadIdx.x] = atomicAdd(&g_cursor[threadIdx.x], lc[threadIdx.x]);
    __syncthreads();
    if (valid) g_perm[base[t] + rank] = e;
}

// ---------------- weight transpose + tf32 split (once per launch) ----------------
__global__ void k_prep_w(const float* __restrict__ W1, const float* __restrict__ W2) {
    int idx = blockIdx.x * blockDim.x + threadIdx.x;
    const int N1 = 6 * 256 * 128;
    const int N2 = 6 * 128 * 128;
    if (idx < N1) {
        int lt = idx / (256 * 128), rem = idx % (256 * 128);
        int k = rem / 128, n = rem % 128;
        float v = W1[idx];
        float hi = tf32_rna(v);
        float lo = tf32_rna(v - hi);
        int o = lt * 32768 + n * 256 + k;
        g_W1T_hi[o] = hi; g_W1T_lo[o] = lo;
    } else if (idx < N1 + N2) {
        int i2 = idx - N1;
        int lt = i2 / (128 * 128), rem = i2 % (128 * 128);
        int k = rem / 128, n = rem % 128;
        float v = W2[i2];
        float hi = tf32_rna(v);
        float lo = tf32_rna(v - hi);
        int o = lt * 16384 + n * 128 + k;
        g_W2T_hi[o] = hi; g_W2T_lo[o] = lo;
    }
}

// ---------------- h = relu(x @ W_in + b_in) ----------------
__global__ void k_init(const float* __restrict__ x, const float* __restrict__ Win,
                       const float* __restrict__ bin) {
    __shared__ float sW[FEAT * H];
    __shared__ float sb[H];
    for (int i = threadIdx.x; i < FEAT * H; i += blockDim.x) sW[i] = Win[i];
    if (threadIdx.x < H) sb[threadIdx.x] = bin[threadIdx.x];
    __syncthreads();
    int idx = blockIdx.x * blockDim.x + threadIdx.x;
    if (idx >= N_NODES * H) return;
    int n = idx >> 7, c = idx & 127;
    float4 xr = ((const float4*)x)[n];
    float v = sb[c] + xr.x * sW[c] + xr.y * sW[H + c] + xr.z * sW[2 * H + c] + xr.w * sW[3 * H + c];
    g_h[idx] = fmaxf(v, 0.0f);
}

__global__ void k_zero_agg() {
    int i = blockIdx.x * blockDim.x + threadIdx.x;
    if (i < N_NODES * H) g_agg[i] = 0.0f;
}

// ---------------- edge MLP on mma.sync tf32x3 ----------------
// smem (floats):
//   sHID: 128 x 132            (offset 0)          67584 B  (phase1 A chunk aliases rows of this)
//   sBH : 128 x 36             (offset 16896 f)    18432 B
//   sBL : 128 x 36             (offset 21504 f)    18432 B
//   sSrc(128i) sDst(128i) sB1(128f) sB2(128f)      2048 B
#define F_HID  0
#define F_BH   16896
#define F_BL   (16896 + 4608)
#define F_META (16896 + 9216)
#define EDGE_SMEM ((F_META + 512) * 4)

__global__ __launch_bounds__(256, 2)
void k_edge_tc(const int* __restrict__ edge_index,
               const float* __restrict__ b1, const float* __restrict__ b2, int l) {
    extern __shared__ float smf[];
    float* sHID = smf + F_HID;        // stride 132 (phase2) / A chunk stride 36 (phase1)
    float* sBH  = smf + F_BH;         // [n][36]
    float* sBL  = smf + F_BL;         // [n][36]
    int*   sSrc = (int*)(smf + F_META);
    int*   sDst = sSrc + 128;
    float* sB1  = (float*)(sDst + 128);
    float* sB2  = sB1 + 128;

    int tid = threadIdx.x;
    int w = tid >> 5, lane = tid & 31;
    int gid = lane >> 2, tig = lane & 3;

    int cnt0 = g_cnt[0];
    int nb0 = (cnt0 + TILE_E - 1) / TILE_E;
    int type, start, cnt, permBase;
    if ((int)blockIdx.x < nb0) {
        type = 0; start = blockIdx.x * TILE_E; cnt = cnt0; permBase = 0;
    } else {
        type = 1; start = ((int)blockIdx.x - nb0) * TILE_E;
        cnt = N_EDGESC - cnt0; permBase = cnt0;
        if (start >= cnt) return;
    }
    int lt = l * NT + type;

    if (tid < 128) {
        int g = start + tid; int s = -1, d = -1;
        if (g < cnt) { int e = g_perm[permBase + g]; s = edge_index[e]; d = edge_index[N_EDGESC + e]; }
        sSrc[tid] = s;
        sDst[tid] = d;
    } else {
        int c = tid - 128;
        sB1[c] = b1[lt * H + c];
        sB2[c] = b2[lt * H + c];
    }
    __syncthreads();

    float acc[16][4];
#pragma unroll
    for (int j = 0; j < 16; ++j)
#pragma unroll
        for (int q = 0; q < 4; ++q) acc[j][q] = 0.f;

    int rowA0 = w * 16 + gid;   // this warp's fragment rows
    int rowA1 = rowA0 + 8;

    // ===== GEMM1: cat[128x256] @ W1[256x128], 8 K-chunks of 32 =====
    const float* w1h = g_W1T_hi + (size_t)lt * 32768;
    const float* w1l = g_W1T_lo + (size_t)lt * 32768;
    for (int kc = 0; kc < 8; ++kc) {
        // stage A chunk (fp32 raw): sHID used as [row][36]
        for (int t = tid; t < 1024; t += 256) {
            int r = t >> 3, q = t & 7;
            int node = (kc < 4) ? sSrc[r] : sDst[r];
            float4 v = make_float4(0.f, 0.f, 0.f, 0.f);
            if (node >= 0) v = *(const float4*)(g_h + (size_t)node * H + (kc & 3) * 32 + q * 4);
            *(float4*)(sHID + r * 36 + q * 4) = v;
        }
        // stage B chunk (pre-split tf32): [n][36]
        for (int t = tid; t < 1024; t += 256) {
            int n = t >> 3, q = t & 7;
            *(float4*)(sBH + n * 36 + q * 4) = *(const float4*)(w1h + n * 256 + kc * 32 + q * 4);
            *(float4*)(sBL + n * 36 + q * 4) = *(const float4*)(w1l + n * 256 + kc * 32 + q * 4);
        }
        __syncthreads();
#pragma unroll
        for (int s = 0; s < 4; ++s) {
            int ka = s * 8 + tig;
            uint32_t ah[4], al[4];
            split_bits(sHID[rowA0 * 36 + ka],     ah[0], al[0]);
            split_bits(sHID[rowA1 * 36 + ka],     ah[1], al[1]);
            split_bits(sHID[rowA0 * 36 + ka + 4], ah[2], al[2]);
            split_bits(sHID[rowA1 * 36 + ka + 4], ah[3], al[3]);
#pragma unroll
            for (int j = 0; j < 16; ++j) {
                int nb = (j * 8 + gid) * 36 + s * 8 + tig;
                uint32_t bh0 = __float_as_uint(sBH[nb]);
                uint32_t bh1 = __float_as_uint(sBH[nb + 4]);
                uint32_t bl0 = __float_as_uint(sBL[nb]);
                uint32_t bl1 = __float_as_uint(sBL[nb + 4]);
                mma_tf32(acc[j], ah[0], ah[1], ah[2], ah[3], bh0, bh1);
                mma_tf32(acc[j], al[0], al[1], al[2], al[3], bh0, bh1);
                mma_tf32(acc[j], ah[0], ah[1], ah[2], ah[3], bl0, bl1);
            }
        }
        __syncthreads();
    }

    // epilogue1: hidden = relu(acc + b1) -> sHID [row][132]; reset acc
#pragma unroll
    for (int j = 0; j < 16; ++j) {
        int col = j * 8 + 2 * tig;
        float ba = sB1[col], bb = sB1[col + 1];
        float2 v0 = make_float2(fmaxf(acc[j][0] + ba, 0.f), fmaxf(acc[j][1] + bb, 0.f));
        float2 v1 = make_float2(fmaxf(acc[j][2] + ba, 0.f), fmaxf(acc[j][3] + bb, 0.f));
        *(float2*)(sHID + rowA0 * 132 + col) = v0;
        *(float2*)(sHID + rowA1 * 132 + col) = v1;
        acc[j][0] = acc[j][1] = acc[j][2] = acc[j][3] = 0.f;
    }
    // (A frags for GEMM2 are read only from this warp's own rows — no cross-warp sync needed;
    //  the per-chunk __syncthreads below covers the B staging.)

    // ===== GEMM2: hidden[128x128] @ W2[128x128], 4 K-chunks of 32 =====
    const float* w2h = g_W2T_hi + (size_t)lt * 16384;
    const float* w2l = g_W2T_lo + (size_t)lt * 16384;
    for (int kc = 0; kc < 4; ++kc) {
        __syncthreads();  // previous chunk's B reads done before overwrite
        for (int t = tid; t < 1024; t += 256) {
            int n = t >> 3, q = t & 7;
            *(float4*)(sBH + n * 36 + q * 4) = *(const float4*)(w2h + n * 128 + kc * 32 + q * 4);
            *(float4*)(sBL + n * 36 + q * 4) = *(const float4*)(w2l + n * 128 + kc * 32 + q * 4);
        }
        __syncthreads();
#pragma unroll
        for (int s = 0; s < 4; ++s) {
            int ka = kc * 32 + s * 8 + tig;
            uint32_t ah[4], al[4];
            split_bits(sHID[rowA0 * 132 + ka],     ah[0], al[0]);
            split_bits(sHID[rowA1 * 132 + ka],     ah[1], al[1]);
            split_bits(sHID[rowA0 * 132 + ka + 4], ah[2], al[2]);
            split_bits(sHID[rowA1 * 132 + ka + 4], ah[3], al[3]);
#pragma unroll
            for (int j = 0; j < 16; ++j) {
                int nb = (j * 8 + gid) * 36 + s * 8 + tig;
                uint32_t bh0 = __float_as_uint(sBH[nb]);
                uint32_t bh1 = __float_as_uint(sBH[nb + 4]);
                uint32_t bl0 = __float_as_uint(sBL[nb]);
                uint32_t bl1 = __float_as_uint(sBL[nb + 4]);
                mma_tf32(acc[j], ah[0], ah[1], ah[2], ah[3], bh0, bh1);
                mma_tf32(acc[j], al[0], al[1], al[2], al[3], bh0, bh1);
                mma_tf32(acc[j], ah[0], ah[1], ah[2], ah[3], bl0, bl1);
            }
        }
    }

    // epilogue2: msgs = acc + b2 -> red into agg[dst]
    int d0 = sDst[rowA0];
    int d1 = sDst[rowA1];
#pragma unroll
    for (int j = 0; j < 16; ++j) {
        int col = j * 8 + 2 * tig;
        float ba = sB2[col], bb = sB2[col + 1];
        if (d0 >= 0) red2(g_agg + (size_t)d0 * H + col, acc[j][0] + ba, acc[j][1] + bb);
        if (d1 >= 0) red2(g_agg + (size_t)d1 * H + col, acc[j][2] + ba, acc[j][3] + bb);
    }
}

// ---------------- GRU GEMMs (scalar FFMA, known good) ----------------
__global__ __launch_bounds__(256)
void k_gru_gemm(const float* __restrict__ Wih, const float* __restrict__ bih,
                const float* __restrict__ Whh, const float* __restrict__ bhh, int l) {
    extern __shared__ float smemf[];
    float* sA = smemf;
    float* sW = smemf + 64 * H;

    const float* A; const float* W; const float* b; float* C;
    if (blockIdx.z == 0) { A = g_agg; W = Wih + (size_t)l * H * 3 * H; b = bih + l * 3 * H; C = g_gi; }
    else                 { A = g_h;   W = Whh + (size_t)l * H * 3 * H; b = bhh + l * 3 * H; C = g_gh; }

    int m0 = blockIdx.x * 64;
    int c0 = blockIdx.y * 128;

    for (int t = threadIdx.x; t < 64 * 32; t += 256) {
        int r = t >> 5, c4 = t & 31;
        int m = m0 + r;
        float4 v = make_float4(0.f, 0.f, 0.f, 0.f);
        if (m < N_NODES) v = ((const float4*)(A + (size_t)m * H))[c4];
        ((float4*)sA)[t] = v;
    }

    int ty = threadIdx.x >> 4, tx = threadIdx.x & 15;
    const float4* sW4 = (const float4*)sW;
    float acc[4][8];
#pragma unroll
    for (int i = 0; i < 4; ++i)
#pragma unroll
        for (int j = 0; j < 8; ++j) acc[i][j] = 0.f;

    for (int kc = 0; kc < 4; ++kc) {
        __syncthreads();
        for (int t = threadIdx.x; t < 32 * 32; t += 256) {
            int wr = t >> 5;
            ((float4*)sW)[t] = *(const float4*)(W + (kc * 32 + wr) * (3 * H) + c0 + (t & 31) * 4);
        }
        __syncthreads();
#pragma unroll
        for (int k = 0; k < 32; ++k) {
            float4 bA = sW4[k * 32 + tx];
            float4 bB = sW4[k * 32 + 16 + tx];
            float bv[8] = {bA.x, bA.y, bA.z, bA.w, bB.x, bB.y, bB.z, bB.w};
            float av[4];
#pragma unroll
            for (int i = 0; i < 4; ++i) av[i] = sA[(ty + 16 * i) * H + kc * 32 + k];
#pragma unroll
            for (int i = 0; i < 4; ++i)
#pragma unroll
                for (int j = 0; j < 8; ++j) acc[i][j] += av[i] * bv[j];
        }
    }

#pragma unroll
    for (int i = 0; i < 4; ++i) {
        int m = m0 + ty + 16 * i;
        if (m >= N_NODES) continue;
#pragma unroll
        for (int j = 0; j < 8; ++j) {
            int col = tx * 4 + (j >> 2) * 64 + (j & 3);
            C[(size_t)m * 384 + c0 + col] = acc[i][j] + b[c0 + col];
        }
    }
}

__global__ void k_gru_combine() {
    int idx = blockIdx.x * blockDim.x + threadIdx.x;
    if (idx >= N_NODES * H) return;
    int n = idx >> 7, c = idx & 127;
    const float* gi = g_gi + (size_t)n * 384;
    const float* gh = g_gh + (size_t)n * 384;
    float r = sigm(gi[c] + gh[c]);
    float z = sigm(gi[128 + c] + gh[128 + c]);
    float nn = tanhf(gi[256 + c] + r * gh[256 + c]);
    g_h[idx] = (1.0f - z) * nn + z * g_h[idx];
}

// ---------------- readout ----------------
__global__ __launch_bounds__(256)
void k_readout(const float* __restrict__ Wr1, const float* __restrict__ br1,
               const float* __restrict__ Wr2, const float* __restrict__ br2,
               float* __restrict__ out, int nd) {
    extern __shared__ float smemf[];
    float* sW1 = smemf;
    float* sb1 = sW1 + H * H;
    float* sW2 = sb1 + H;
    float* sHrow = sW2 + H;

    for (int t = threadIdx.x; t < (H * H) / 4; t += blockDim.x)
        ((float4*)sW1)[t] = ((const float4*)Wr1)[t];
    if (threadIdx.x < H) {
        sb1[threadIdx.x] = br1[threadIdx.x];
        sW2[threadIdx.x] = Wr2[threadIdx.x];
    }
    __syncthreads();

    int w = threadIdx.x >> 5, lane = threadIdx.x & 31;
    float* myrow = sHrow + w * H;
    float b2v = br2[0];

    for (int n = blockIdx.x * 8 + w; n < nd; n += gridDim.x * 8) {
        ((float4*)myrow)[lane] = ((const float4*)(g_h + (size_t)n * H))[lane];
        __syncwarp();
        float hid0 = 0.f, hid1 = 0.f, hid2 = 0.f, hid3 = 0.f;
#pragma unroll 4
        for (int k = 0; k < H; ++k) {
            float a = myrow[k];
            float4 wv = ((const float4*)sW1)[k * 32 + lane];
            hid0 += a * wv.x; hid1 += a * wv.y; hid2 += a * wv.z; hid3 += a * wv.w;
        }
        float4 w2 = ((const float4*)sW2)[lane];
        float p = fmaxf(hid0 + sb1[lane * 4 + 0], 0.f) * w2.x
                + fmaxf(hid1 + sb1[lane * 4 + 1], 0.f) * w2.y
                + fmaxf(hid2 + sb1[lane * 4 + 2], 0.f) * w2.z
                + fmaxf(hid3 + sb1[lane * 4 + 3], 0.f) * w2.w;
#pragma unroll
        for (int o = 16; o > 0; o >>= 1) p += __shfl_down_sync(0xffffffffu, p, o);
        if (lane == 0) out[n] = p + b2v;
        __syncwarp();
    }
}

// ---------------- launch ----------------
extern "C" void kernel_launch(void* const* d_in, const int* in_sizes, int n_in,
                              void* d_out, int out_size) {
    int base = (n_in >= 18) ? 4 : 3;
    const float* x          = (const float*)d_in[0];
    const int*   edge_index = (const int*)d_in[1];
    const int*   edge_type  = (const int*)d_in[2];
    const float* W_in = (const float*)d_in[base + 0];
    const float* b_in = (const float*)d_in[base + 1];
    const float* W1   = (const float*)d_in[base + 2];
    const float* b1   = (const float*)d_in[base + 3];
    const float* W2   = (const float*)d_in[base + 4];
    const float* b2   = (const float*)d_in[base + 5];
    const float* W_ih = (const float*)d_in[base + 6];
    const float* b_ih = (const float*)d_in[base + 7];
    const float* W_hh = (const float*)d_in[base + 8];
    const float* b_hh = (const float*)d_in[base + 9];
    const float* Wr1  = (const float*)d_in[base + 10];
    const float* br1  = (const float*)d_in[base + 11];
    const float* Wr2  = (const float*)d_in[base + 12];
    const float* br2  = (const float*)d_in[base + 13];
    float* out = (float*)d_out;

    const int GRU_SMEM  = (64 * 128 + 32 * 128) * 4;
    const int READ_SMEM = (128 * 128 + 128 + 128 + 8 * 128) * 4;
    cudaFuncSetAttribute(k_edge_tc, cudaFuncAttributeMaxDynamicSharedMemorySize, EDGE_SMEM);
    cudaFuncSetAttribute(k_gru_gemm, cudaFuncAttributeMaxDynamicSharedMemorySize, GRU_SMEM);
    cudaFuncSetAttribute(k_readout,  cudaFuncAttributeMaxDynamicSharedMemorySize, READ_SMEM);

    k_zero_cnt<<<1, 32>>>();
    k_count<<<(N_EDGESC + 255) / 256, 256>>>(edge_type);
    k_seed<<<1, 1>>>();
    k_scatter<<<(N_EDGESC + 255) / 256, 256>>>(edge_type);

    k_prep_w<<<(6 * 256 * 128 + 6 * 128 * 128 + 255) / 256, 256>>>(W1, W2);
    k_init<<<(N_NODES * H + 255) / 256, 256>>>(x, W_in, b_in);

    const int NEL = N_NODES * H;
    const int EDGE_BLOCKS = N_EDGESC / TILE_E + 2;
    for (int l = 0; l < 3; ++l) {
        k_zero_agg<<<(NEL + 255) / 256, 256>>>();
        k_edge_tc<<<EDGE_BLOCKS, 256, EDGE_SMEM>>>(edge_index, b1, b2, l);
        dim3 gg((N_NODES + 63) / 64, 3, 2);
        k_gru_gemm<<<gg, 256, GRU_SMEM>>>(W_ih, b_ih, W_hh, b_hh, l);
        k_gru_combine<<<(NEL + 255) / 256, 256>>>();
    }

    k_readout<<<625, 256, READ_SMEM>>>(Wr1, br1, Wr2, br2, out, out_size);
}

// round 10
// speedup vs baseline: 2.3826x; 1.8375x over previous
#include <cuda_runtime.h>
#include <cuda_bf16.h>
#include <math.h>
#include <stdint.h>

#define N_NODES 50000
#define N_EDGESC 400000
#define H 128
#define NT 2
#define FEAT 4
#define TILE_E 128

// ---------------- device scratch (no runtime allocation) ----------------
__device__ float g_h[N_NODES * H];
__device__ float g_agg[N_NODES * H];
__device__ float g_gi[N_NODES * 3 * H];
__device__ float g_gh[N_NODES * 3 * H];
__device__ int   g_perm[N_EDGESC];
__device__ int   g_cnt[2];
__device__ int   g_cursor[2];
// transposed, bf16 hi/lo packed weights: word [lt][n][kw] holds bf16(k=2kw), bf16(k=2kw+1)
__device__ uint32_t g_W1B_hi[6 * 128 * 128];
__device__ uint32_t g_W1B_lo[6 * 128 * 128];
__device__ uint32_t g_W2B_hi[6 * 128 * 64];
__device__ uint32_t g_W2B_lo[6 * 128 * 64];

__device__ __forceinline__ float sigm(float v) { return 1.0f / (1.0f + expf(-v)); }

// split (x,y) into packed bf16x2 hi word + bf16x2 lo (residual) word; even k in low half
__device__ __forceinline__ void split_pack(float x, float y, uint32_t& hi, uint32_t& lo) {
    __nv_bfloat162 h = __floats2bfloat162_rn(x, y);
    hi = reinterpret_cast<uint32_t&>(h);
    float rx = x - __low2float(h);
    float ry = y - __high2float(h);
    __nv_bfloat162 l = __floats2bfloat162_rn(rx, ry);
    lo = reinterpret_cast<uint32_t&>(l);
}

__device__ __forceinline__ void mma_bf16(float* c, uint32_t a0, uint32_t a1, uint32_t a2,
                                         uint32_t a3, uint32_t b0, uint32_t b1) {
    asm volatile(
        "mma.sync.aligned.m16n8k16.row.col.f32.bf16.bf16.f32 "
        "{%0,%1,%2,%3}, {%4,%5,%6,%7}, {%8,%9}, {%0,%1,%2,%3};"
        : "+f"(c[0]), "+f"(c[1]), "+f"(c[2]), "+f"(c[3])
        : "r"(a0), "r"(a1), "r"(a2), "r"(a3), "r"(b0), "r"(b1));
}

__device__ __forceinline__ void red2(float* p, float a, float b) {
    asm volatile("red.global.add.v2.f32 [%0], {%1, %2};" :: "l"(p), "f"(a), "f"(b) : "memory");
}

// ---------------- edge partition by type ----------------
__global__ void k_zero_cnt() { if (threadIdx.x < 2) g_cnt[threadIdx.x] = 0; }

__global__ void k_count(const int* __restrict__ et) {
    __shared__ int lc[2];
    if (threadIdx.x < 2) lc[threadIdx.x] = 0;
    __syncthreads();
    int e = blockIdx.x * blockDim.x + threadIdx.x;
    if (e < N_EDGESC) atomicAdd(&lc[et[e]], 1);
    __syncthreads();
    if (threadIdx.x < 2) atomicAdd(&g_cnt[threadIdx.x], lc[threadIdx.x]);
}

__global__ void k_seed() { g_cursor[0] = 0; g_cursor[1] = g_cnt[0]; }

__global__ void k_scatter(const int* __restrict__ et) {
    __shared__ int lc[2];
    __shared__ int base[2];
    if (threadIdx.x < 2) lc[threadIdx.x] = 0;
    __syncthreads();
    int e = blockIdx.x * blockDim.x + threadIdx.x;
    int t = 0, rank = 0;
    bool valid = (e < N_EDGESC);
    if (valid) { t = et[e]; rank = atomicAdd(&lc[t], 1); }
    __syncthreads();
    if (threadIdx.x < 2) base[threadIdx.x] = atomicAdd(&g_cursor[threadIdx.x], lc[threadIdx.x]);
    __syncthreads();
    if (valid) g_perm[base[t] + rank] = e;
}

// ---------------- weight transpose + bf16 split-pack (once per launch) ----------------
__global__ void k_prep_w(const float* __restrict__ W1, const float* __restrict__ W2) {
    int idx = blockIdx.x * blockDim.x + threadIdx.x;
    const int NW1 = 6 * 128 * 128;   // packed words for W1
    const int NW2 = 6 * 128 * 64;    // packed words for W2
    if (idx < NW1) {
        int lt = idx >> 14, rem = idx & 16383;
        int n = rem >> 7, kw = rem & 127;
        const float* base = W1 + (size_t)lt * 32768;
        float v0 = base[(2 * kw) * 128 + n];
        float v1 = base[(2 * kw + 1) * 128 + n];
        uint32_t hi, lo;
        split_pack(v0, v1, hi, lo);
        int o = lt * 16384 + n * 128 + kw;
        g_W1B_hi[o] = hi; g_W1B_lo[o] = lo;
    } else if (idx < NW1 + NW2) {
        int i2 = idx - NW1;
        int lt = i2 >> 13, rem = i2 & 8191;
        int n = rem >> 6, kw = rem & 63;
        const float* base = W2 + (size_t)lt * 16384;
        float v0 = base[(2 * kw) * 128 + n];
        float v1 = base[(2 * kw + 1) * 128 + n];
        uint32_t hi, lo;
        split_pack(v0, v1, hi, lo);
        int o = lt * 8192 + n * 64 + kw;
        g_W2B_hi[o] = hi; g_W2B_lo[o] = lo;
    }
}

// ---------------- h = relu(x @ W_in + b_in) ----------------
__global__ void k_init(const float* __restrict__ x, const float* __restrict__ Win,
                       const float* __restrict__ bin) {
    __shared__ float sW[FEAT * H];
    __shared__ float sb[H];
    for (int i = threadIdx.x; i < FEAT * H; i += blockDim.x) sW[i] = Win[i];
    if (threadIdx.x < H) sb[threadIdx.x] = bin[threadIdx.x];
    __syncthreads();
    int idx = blockIdx.x * blockDim.x + threadIdx.x;
    if (idx >= N_NODES * H) return;
    int n = idx >> 7, c = idx & 127;
    float4 xr = ((const float4*)x)[n];
    float v = sb[c] + xr.x * sW[c] + xr.y * sW[H + c] + xr.z * sW[2 * H + c] + xr.w * sW[3 * H + c];
    g_h[idx] = fmaxf(v, 0.0f);
}

__global__ void k_zero_agg() {
    int i = blockIdx.x * blockDim.x + threadIdx.x;
    if (i < N_NODES * H) g_agg[i] = 0.0f;
}

// ---------------- edge MLP on mma.sync bf16 (hi/lo x3) ----------------
// smem (uint32 words):
//   sAh [128][68]  — GEMM1 A chunk staging (kw 0..15) / hidden packed hi (kw 0..63)
//   sAl [128][68]  — same, lo
//   sBh [128][20]  — B chunk hi   sBl [128][20] — B chunk lo
//   meta: sSrc(128) sDst(128) sB1(128f) sB2(128f)
#define A_STR 68
#define B_STR 20
#define F_AH 0
#define F_AL (128 * A_STR)
#define F_BH (2 * 128 * A_STR)
#define F_BL (F_BH + 128 * B_STR)
#define F_META (F_BL + 128 * B_STR)
#define EDGE_SMEM ((F_META + 512) * 4)

__global__ __launch_bounds__(256, 2)
void k_edge_tc(const int* __restrict__ edge_index,
               const float* __restrict__ b1, const float* __restrict__ b2, int l) {
    extern __shared__ uint32_t smw[];
    uint32_t* sAh = smw + F_AH;
    uint32_t* sAl = smw + F_AL;
    uint32_t* sBh = smw + F_BH;
    uint32_t* sBl = smw + F_BL;
    int*   sSrc = (int*)(smw + F_META);
    int*   sDst = sSrc + 128;
    float* sB1  = (float*)(sDst + 128);
    float* sB2  = sB1 + 128;

    int tid = threadIdx.x;
    int w = tid >> 5, lane = tid & 31;
    int gid = lane >> 2, tig = lane & 3;

    int cnt0 = g_cnt[0];
    int nb0 = (cnt0 + TILE_E - 1) / TILE_E;
    int type, start, cnt, permBase;
    if ((int)blockIdx.x < nb0) {
        type = 0; start = blockIdx.x * TILE_E; cnt = cnt0; permBase = 0;
    } else {
        type = 1; start = ((int)blockIdx.x - nb0) * TILE_E;
        cnt = N_EDGESC - cnt0; permBase = cnt0;
        if (start >= cnt) return;
    }
    int lt = l * NT + type;

    if (tid < 128) {
        int g = start + tid; int s = -1, d = -1;
        if (g < cnt) { int e = g_perm[permBase + g]; s = edge_index[e]; d = edge_index[N_EDGESC + e]; }
        sSrc[tid] = s;
        sDst[tid] = d;
    } else {
        int c = tid - 128;
        sB1[c] = b1[lt * H + c];
        sB2[c] = b2[lt * H + c];
    }
    __syncthreads();

    float acc[16][4];
#pragma unroll
    for (int j = 0; j < 16; ++j)
#pragma unroll
        for (int q = 0; q < 4; ++q) acc[j][q] = 0.f;

    int rA0 = w * 16 + gid;
    int rA1 = rA0 + 8;

    // ===== GEMM1: cat[128x256] @ W1[256x128], 8 K-chunks of 32 =====
    const uint32_t* w1h = g_W1B_hi + (size_t)lt * 16384;
    const uint32_t* w1l = g_W1B_lo + (size_t)lt * 16384;
    for (int kc = 0; kc < 8; ++kc) {
        // stage A chunk: gather + split-pack to bf16 hi/lo (16 words per row)
        for (int i = tid; i < 1024; i += 256) {
            int r = i >> 3, q = i & 7;
            int node = (kc < 4) ? sSrc[r] : sDst[r];
            float4 v = make_float4(0.f, 0.f, 0.f, 0.f);
            if (node >= 0) v = *(const float4*)(g_h + (size_t)node * H + (kc & 3) * 32 + q * 4);
            uint32_t h0, l0, h1, l1;
            split_pack(v.x, v.y, h0, l0);
            split_pack(v.z, v.w, h1, l1);
            *(uint2*)(sAh + r * A_STR + q * 2) = make_uint2(h0, h1);
            *(uint2*)(sAl + r * A_STR + q * 2) = make_uint2(l0, l1);
        }
        // stage B chunk: pre-packed, straight copy (16 words per n-row)
        {
            int n = tid >> 1, off = (tid & 1) * 8;
            const uint4* sh = (const uint4*)(w1h + n * 128 + kc * 16 + off);
            const uint4* sl = (const uint4*)(w1l + n * 128 + kc * 16 + off);
            *(uint4*)(sBh + n * B_STR + off)     = sh[0];
            *(uint4*)(sBh + n * B_STR + off + 4) = sh[1];
            *(uint4*)(sBl + n * B_STR + off)     = sl[0];
            *(uint4*)(sBl + n * B_STR + off + 4) = sl[1];
        }
        __syncthreads();
#pragma unroll
        for (int s = 0; s < 2; ++s) {
            int kwb = 8 * s;
            uint32_t ah0 = sAh[rA0 * A_STR + kwb + tig];
            uint32_t ah1 = sAh[rA1 * A_STR + kwb + tig];
            uint32_t ah2 = sAh[rA0 * A_STR + kwb + tig + 4];
            uint32_t ah3 = sAh[rA1 * A_STR + kwb + tig + 4];
            uint32_t al0 = sAl[rA0 * A_STR + kwb + tig];
            uint32_t al1 = sAl[rA1 * A_STR + kwb + tig];
            uint32_t al2 = sAl[rA0 * A_STR + kwb + tig + 4];
            uint32_t al3 = sAl[rA1 * A_STR + kwb + tig + 4];
#pragma unroll
            for (int j = 0; j < 16; ++j) {
                int nb = (j * 8 + gid) * B_STR + kwb + tig;
                uint32_t bh0 = sBh[nb], bh1 = sBh[nb + 4];
                uint32_t bl0 = sBl[nb], bl1 = sBl[nb + 4];
                mma_bf16(acc[j], ah0, ah1, ah2, ah3, bh0, bh1);
                mma_bf16(acc[j], al0, al1, al2, al3, bh0, bh1);
                mma_bf16(acc[j], ah0, ah1, ah2, ah3, bl0, bl1);
            }
        }
        __syncthreads();
    }

    // epilogue1: hidden = relu(acc + b1), pack straight to bf16 hi/lo in sAh/sAl
#pragma unroll
    for (int j = 0; j < 16; ++j) {
        int col = j * 8 + 2 * tig;
        float ba = sB1[col], bb = sB1[col + 1];
        float v0x = fmaxf(acc[j][0] + ba, 0.f), v0y = fmaxf(acc[j][1] + bb, 0.f);
        float v1x = fmaxf(acc[j][2] + ba, 0.f), v1y = fmaxf(acc[j][3] + bb, 0.f);
        int kw = j * 4 + tig;
        uint32_t h, lo;
        split_pack(v0x, v0y, h, lo);
        sAh[rA0 * A_STR + kw] = h; sAl[rA0 * A_STR + kw] = lo;
        split_pack(v1x, v1y, h, lo);
        sAh[rA1 * A_STR + kw] = h; sAl[rA1 * A_STR + kw] = lo;
        acc[j][0] = acc[j][1] = acc[j][2] = acc[j][3] = 0.f;
    }
    // (each warp reads only its own 16 rows in GEMM2 — no cross-warp A hazard)

    // ===== GEMM2: hidden[128x128] @ W2[128x128], 4 K-chunks of 32 =====
    const uint32_t* w2h = g_W2B_hi + (size_t)lt * 8192;
    const uint32_t* w2l = g_W2B_lo + (size_t)lt * 8192;
    for (int kc = 0; kc < 4; ++kc) {
        {
            int n = tid >> 1, off = (tid & 1) * 8;
            const uint4* sh = (const uint4*)(w2h + n * 64 + kc * 16 + off);
            const uint4* sl = (const uint4*)(w2l + n * 64 + kc * 16 + off);
            *(uint4*)(sBh + n * B_STR + off)     = sh[0];
            *(uint4*)(sBh + n * B_STR + off + 4) = sh[1];
            *(uint4*)(sBl + n * B_STR + off)     = sl[0];
            *(uint4*)(sBl + n * B_STR + off + 4) = sl[1];
        }
        __syncthreads();
#pragma unroll
        for (int s = 0; s < 2; ++s) {
            int kwb = kc * 16 + 8 * s;
            uint32_t ah0 = sAh[rA0 * A_STR + kwb + tig];
            uint32_t ah1 = sAh[rA1 * A_STR + kwb + tig];
            uint32_t ah2 = sAh[rA0 * A_STR + kwb + tig + 4];
            uint32_t ah3 = sAh[rA1 * A_STR + kwb + tig + 4];
            uint32_t al0 = sAl[rA0 * A_STR + kwb + tig];
            uint32_t al1 = sAl[rA1 * A_STR + kwb + tig];
            uint32_t al2 = sAl[rA0 * A_STR + kwb + tig + 4];
            uint32_t al3 = sAl[rA1 * A_STR + kwb + tig + 4];
#pragma unroll
            for (int j = 0; j < 16; ++j) {
                int nb = (j * 8 + gid) * B_STR + 8 * s + tig;
                uint32_t bh0 = sBh[nb], bh1 = sBh[nb + 4];
                uint32_t bl0 = sBl[nb], bl1 = sBl[nb + 4];
                mma_bf16(acc[j], ah0, ah1, ah2, ah3, bh0, bh1);
                mma_bf16(acc[j], al0, al1, al2, al3, bh0, bh1);
                mma_bf16(acc[j], ah0, ah1, ah2, ah3, bl0, bl1);
            }
        }
        __syncthreads();
    }

    // epilogue2: msgs = acc + b2 -> red into agg[dst]
    int d0 = sDst[rA0];
    int d1 = sDst[rA1];
#pragma unroll
    for (int j = 0; j < 16; ++j) {
        int col = j * 8 + 2 * tig;
        float ba = sB2[col], bb = sB2[col + 1];
        if (d0 >= 0) red2(g_agg + (size_t)d0 * H + col, acc[j][0] + ba, acc[j][1] + bb);
        if (d1 >= 0) red2(g_agg + (size_t)d1 * H + col, acc[j][2] + ba, acc[j][3] + bb);
    }
}

// ---------------- GRU GEMMs (scalar FFMA, known good) ----------------
__global__ __launch_bounds__(256)
void k_gru_gemm(const float* __restrict__ Wih, const float* __restrict__ bih,
                const float* __restrict__ Whh, const float* __restrict__ bhh, int l) {
    extern __shared__ float smemf[];
    float* sA = smemf;
    float* sW = smemf + 64 * H;

    const float* A; const float* W; const float* b; float* C;
    if (blockIdx.z == 0) { A = g_agg; W = Wih + (size_t)l * H * 3 * H; b = bih + l * 3 * H; C = g_gi; }
    else                 { A = g_h;   W = Whh + (size_t)l * H * 3 * H; b = bhh + l * 3 * H; C = g_gh; }

    int m0 = blockIdx.x * 64;
    int c0 = blockIdx.y * 128;

    for (int t = threadIdx.x; t < 64 * 32; t += 256) {
        int r = t >> 5, c4 = t & 31;
        int m = m0 + r;
        float4 v = make_float4(0.f, 0.f, 0.f, 0.f);
        if (m < N_NODES) v = ((const float4*)(A + (size_t)m * H))[c4];
        ((float4*)sA)[t] = v;
    }

    int ty = threadIdx.x >> 4, tx = threadIdx.x & 15;
    const float4* sW4 = (const float4*)sW;
    float acc[4][8];
#pragma unroll
    for (int i = 0; i < 4; ++i)
#pragma unroll
        for (int j = 0; j < 8; ++j) acc[i][j] = 0.f;

    for (int kc = 0; kc < 4; ++kc) {
        __syncthreads();
        for (int t = threadIdx.x; t < 32 * 32; t += 256) {
            int wr = t >> 5;
            ((float4*)sW)[t] = *(const float4*)(W + (kc * 32 + wr) * (3 * H) + c0 + (t & 31) * 4);
        }
        __syncthreads();
#pragma unroll
        for (int k = 0; k < 32; ++k) {
            float4 bA = sW4[k * 32 + tx];
            float4 bB = sW4[k * 32 + 16 + tx];
            float bv[8] = {bA.x, bA.y, bA.z, bA.w, bB.x, bB.y, bB.z, bB.w};
            float av[4];
#pragma unroll
            for (int i = 0; i < 4; ++i) av[i] = sA[(ty + 16 * i) * H + kc * 32 + k];
#pragma unroll
            for (int i = 0; i < 4; ++i)
#pragma unroll
                for (int j = 0; j < 8; ++j) acc[i][j] += av[i] * bv[j];
        }
    }

#pragma unroll
    for (int i = 0; i < 4; ++i) {
        int m = m0 + ty + 16 * i;
        if (m >= N_NODES) continue;
#pragma unroll
        for (int j = 0; j < 8; ++j) {
            int col = tx * 4 + (j >> 2) * 64 + (j & 3);
            C[(size_t)m * 384 + c0 + col] = acc[i][j] + b[c0 + col];
        }
    }
}

__global__ void k_gru_combine() {
    int idx = blockIdx.x * blockDim.x + threadIdx.x;
    if (idx >= N_NODES * H) return;
    int n = idx >> 7, c = idx & 127;
    const float* gi = g_gi + (size_t)n * 384;
    const float* gh = g_gh + (size_t)n * 384;
    float r = sigm(gi[c] + gh[c]);
    float z = sigm(gi[128 + c] + gh[128 + c]);
    float nn = tanhf(gi[256 + c] + r * gh[256 + c]);
    g_h[idx] = (1.0f - z) * nn + z * g_h[idx];
}

// ---------------- readout ----------------
__global__ __launch_bounds__(256)
void k_readout(const float* __restrict__ Wr1, const float* __restrict__ br1,
               const float* __restrict__ Wr2, const float* __restrict__ br2,
               float* __restrict__ out, int nd) {
    extern __shared__ float smemf[];
    float* sW1 = smemf;
    float* sb1 = sW1 + H * H;
    float* sW2 = sb1 + H;
    float* sHrow = sW2 + H;

    for (int t = threadIdx.x; t < (H * H) / 4; t += blockDim.x)
        ((float4*)sW1)[t] = ((const float4*)Wr1)[t];
    if (threadIdx.x < H) {
        sb1[threadIdx.x] = br1[threadIdx.x];
        sW2[threadIdx.x] = Wr2[threadIdx.x];
    }
    __syncthreads();

    int w = threadIdx.x >> 5, lane = threadIdx.x & 31;
    float* myrow = sHrow + w * H;
    float b2v = br2[0];

    for (int n = blockIdx.x * 8 + w; n < nd; n += gridDim.x * 8) {
        ((float4*)myrow)[lane] = ((const float4*)(g_h + (size_t)n * H))[lane];
        __syncwarp();
        float hid0 = 0.f, hid1 = 0.f, hid2 = 0.f, hid3 = 0.f;
#pragma unroll 4
        for (int k = 0; k < H; ++k) {
            float a = myrow[k];
            float4 wv = ((const float4*)sW1)[k * 32 + lane];
            hid0 += a * wv.x; hid1 += a * wv.y; hid2 += a * wv.z; hid3 += a * wv.w;
        }
        float4 w2 = ((const float4*)sW2)[lane];
        float p = fmaxf(hid0 + sb1[lane * 4 + 0], 0.f) * w2.x
                + fmaxf(hid1 + sb1[lane * 4 + 1], 0.f) * w2.y
                + fmaxf(hid2 + sb1[lane * 4 + 2], 0.f) * w2.z
                + fmaxf(hid3 + sb1[lane * 4 + 3], 0.f) * w2.w;
#pragma unroll
        for (int o = 16; o > 0; o >>= 1) p += __shfl_down_sync(0xffffffffu, p, o);
        if (lane == 0) out[n] = p + b2v;
        __syncwarp();
    }
}

// ---------------- launch ----------------
extern "C" void kernel_launch(void* const* d_in, const int* in_sizes, int n_in,
                              void* d_out, int out_size) {
    int base = (n_in >= 18) ? 4 : 3;
    const float* x          = (const float*)d_in[0];
    const int*   edge_index = (const int*)d_in[1];
    const int*   edge_type  = (const int*)d_in[2];
    const float* W_in = (const float*)d_in[base + 0];
    const float* b_in = (const float*)d_in[base + 1];
    const float* W1   = (const float*)d_in[base + 2];
    const float* b1   = (const float*)d_in[base + 3];
    const float* W2   = (const float*)d_in[base + 4];
    const float* b2   = (const float*)d_in[base + 5];
    const float* W_ih = (const float*)d_in[base + 6];
    const float* b_ih = (const float*)d_in[base + 7];
    const float* W_hh = (const float*)d_in[base + 8];
    const float* b_hh = (const float*)d_in[base + 9];
    const float* Wr1  = (const float*)d_in[base + 10];
    const float* br1  = (const float*)d_in[base + 11];
    const float* Wr2  = (const float*)d_in[base + 12];
    const float* br2  = (const float*)d_in[base + 13];
    float* out = (float*)d_out;

    const int GRU_SMEM  = (64 * 128 + 32 * 128) * 4;
    const int READ_SMEM = (128 * 128 + 128 + 128 + 8 * 128) * 4;
    cudaFuncSetAttribute(k_edge_tc, cudaFuncAttributeMaxDynamicSharedMemorySize, EDGE_SMEM);
    cudaFuncSetAttribute(k_gru_gemm, cudaFuncAttributeMaxDynamicSharedMemorySize, GRU_SMEM);
    cudaFuncSetAttribute(k_readout,  cudaFuncAttributeMaxDynamicSharedMemorySize, READ_SMEM);

    k_zero_cnt<<<1, 32>>>();
    k_count<<<(N_EDGESC + 255) / 256, 256>>>(edge_type);
    k_seed<<<1, 1>>>();
    k_scatter<<<(N_EDGESC + 255) / 256, 256>>>(edge_type);

    const int NPW = 6 * 128 * 128 + 6 * 128 * 64;
    k_prep_w<<<(NPW + 255) / 256, 256>>>(W1, W2);
    k_init<<<(N_NODES * H + 255) / 256, 256>>>(x, W_in, b_in);

    const int NEL = N_NODES * H;
    const int EDGE_BLOCKS = N_EDGESC / TILE_E + 2;
    for (int l = 0; l < 3; ++l) {
        k_zero_agg<<<(NEL + 255) / 256, 256>>>();
        k_edge_tc<<<EDGE_BLOCKS, 256, EDGE_SMEM>>>(edge_index, b1, b2, l);
        dim3 gg((N_NODES + 63) / 64, 3, 2);
        k_gru_gemm<<<gg, 256, GRU_SMEM>>>(W_ih, b_ih, W_hh, b_hh, l);
        k_gru_combine<<<(NEL + 255) / 256, 256>>>();
    }

    k_readout<<<625, 256, READ_SMEM>>>(Wr1, br1, Wr2, br2, out, out_size);
}

// round 11
// speedup vs baseline: 2.7311x; 1.1462x over previous
#include <cuda_runtime.h>
#include <cuda_bf16.h>
#include <math.h>
#include <stdint.h>

#define N_NODES 50000
#define N_EDGESC 400000
#define H 128
#define NT 2
#define FEAT 4
#define TILE_E 128

// ---------------- device scratch (no runtime allocation) ----------------
__device__ float g_h[N_NODES * H];
__device__ float g_agg[N_NODES * H];
__device__ float g_gi[N_NODES * 3 * H];
__device__ float g_gh[N_NODES * 3 * H];
__device__ int   g_perm[N_EDGESC];
__device__ int   g_cnt[2];
__device__ int   g_cursor[2];
// transposed, bf16 hi/lo packed weights: word [lt][n][kw] holds bf16(k=2kw), bf16(k=2kw+1)
__device__ uint32_t g_W1B_hi[6 * 128 * 128];
__device__ uint32_t g_W1B_lo[6 * 128 * 128];
__device__ uint32_t g_W2B_hi[6 * 128 * 64];
__device__ uint32_t g_W2B_lo[6 * 128 * 64];
// GRU weights: [sel(ih/hh)][l][n(384)][kw(64)]
__device__ uint32_t g_WGB_hi[2 * 3 * 384 * 64];
__device__ uint32_t g_WGB_lo[2 * 3 * 384 * 64];

__device__ __forceinline__ float sigm(float v) { return 1.0f / (1.0f + expf(-v)); }

// split (x,y) into packed bf16x2 hi word + bf16x2 lo (residual) word; even k in low half
__device__ __forceinline__ void split_pack(float x, float y, uint32_t& hi, uint32_t& lo) {
    __nv_bfloat162 h = __floats2bfloat162_rn(x, y);
    hi = reinterpret_cast<uint32_t&>(h);
    float rx = x - __low2float(h);
    float ry = y - __high2float(h);
    __nv_bfloat162 l = __floats2bfloat162_rn(rx, ry);
    lo = reinterpret_cast<uint32_t&>(l);
}

__device__ __forceinline__ void mma_bf16(float* c, uint32_t a0, uint32_t a1, uint32_t a2,
                                         uint32_t a3, uint32_t b0, uint32_t b1) {
    asm volatile(
        "mma.sync.aligned.m16n8k16.row.col.f32.bf16.bf16.f32 "
        "{%0,%1,%2,%3}, {%4,%5,%6,%7}, {%8,%9}, {%0,%1,%2,%3};"
        : "+f"(c[0]), "+f"(c[1]), "+f"(c[2]), "+f"(c[3])
        : "r"(a0), "r"(a1), "r"(a2), "r"(a3), "r"(b0), "r"(b1));
}

__device__ __forceinline__ void red2(float* p, float a, float b) {
    asm volatile("red.global.add.v2.f32 [%0], {%1, %2};" :: "l"(p), "f"(a), "f"(b) : "memory");
}

// ---------------- edge partition by type ----------------
__global__ void k_zero_cnt() { if (threadIdx.x < 2) g_cnt[threadIdx.x] = 0; }

__global__ void k_count(const int* __restrict__ et) {
    __shared__ int lc[2];
    if (threadIdx.x < 2) lc[threadIdx.x] = 0;
    __syncthreads();
    int e = blockIdx.x * blockDim.x + threadIdx.x;
    if (e < N_EDGESC) atomicAdd(&lc[et[e]], 1);
    __syncthreads();
    if (threadIdx.x < 2) atomicAdd(&g_cnt[threadIdx.x], lc[threadIdx.x]);
}

__global__ void k_seed() { g_cursor[0] = 0; g_cursor[1] = g_cnt[0]; }

__global__ void k_scatter(const int* __restrict__ et) {
    __shared__ int lc[2];
    __shared__ int base[2];
    if (threadIdx.x < 2) lc[threadIdx.x] = 0;
    __syncthreads();
    int e = blockIdx.x * blockDim.x + threadIdx.x;
    int t = 0, rank = 0;
    bool valid = (e < N_EDGESC);
    if (valid) { t = et[e]; rank = atomicAdd(&lc[t], 1); }
    __syncthreads();
    if (threadIdx.x < 2) base[threadIdx.x] = atomicAdd(&g_cursor[threadIdx.x], lc[threadIdx.x]);
    __syncthreads();
    if (valid) g_perm[base[t] + rank] = e;
}

// ---------------- weight transpose + bf16 split-pack (once per launch) ----------------
__global__ void k_prep_w(const float* __restrict__ W1, const float* __restrict__ W2) {
    int idx = blockIdx.x * blockDim.x + threadIdx.x;
    const int NW1 = 6 * 128 * 128;
    const int NW2 = 6 * 128 * 64;
    if (idx < NW1) {
        int lt = idx >> 14, rem = idx & 16383;
        int n = rem >> 7, kw = rem & 127;
        const float* base = W1 + (size_t)lt * 32768;
        float v0 = base[(2 * kw) * 128 + n];
        float v1 = base[(2 * kw + 1) * 128 + n];
        uint32_t hi, lo;
        split_pack(v0, v1, hi, lo);
        int o = lt * 16384 + n * 128 + kw;
        g_W1B_hi[o] = hi; g_W1B_lo[o] = lo;
    } else if (idx < NW1 + NW2) {
        int i2 = idx - NW1;
        int lt = i2 >> 13, rem = i2 & 8191;
        int n = rem >> 6, kw = rem & 63;
        const float* base = W2 + (size_t)lt * 16384;
        float v0 = base[(2 * kw) * 128 + n];
        float v1 = base[(2 * kw + 1) * 128 + n];
        uint32_t hi, lo;
        split_pack(v0, v1, hi, lo);
        int o = lt * 8192 + n * 64 + kw;
        g_W2B_hi[o] = hi; g_W2B_lo[o] = lo;
    }
}

__global__ void k_prep_gru(const float* __restrict__ Wih, const float* __restrict__ Whh) {
    int idx = blockIdx.x * blockDim.x + threadIdx.x;
    const int TOT = 2 * 3 * 384 * 64;
    if (idx >= TOT) return;
    int sel = idx / 73728, rem = idx % 73728;
    int l = rem / 24576, rem2 = rem % 24576;
    int n = rem2 >> 6, kw = rem2 & 63;
    const float* src = (sel ? Whh : Wih) + (size_t)l * H * 3 * H;
    float v0 = src[(2 * kw) * 384 + n];
    float v1 = src[(2 * kw + 1) * 384 + n];
    uint32_t hi, lo;
    split_pack(v0, v1, hi, lo);
    g_WGB_hi[idx] = hi;
    g_WGB_lo[idx] = lo;
}

// ---------------- h = relu(x @ W_in + b_in) ----------------
__global__ void k_init(const float* __restrict__ x, const float* __restrict__ Win,
                       const float* __restrict__ bin) {
    __shared__ float sW[FEAT * H];
    __shared__ float sb[H];
    for (int i = threadIdx.x; i < FEAT * H; i += blockDim.x) sW[i] = Win[i];
    if (threadIdx.x < H) sb[threadIdx.x] = bin[threadIdx.x];
    __syncthreads();
    int idx = blockIdx.x * blockDim.x + threadIdx.x;
    if (idx >= N_NODES * H) return;
    int n = idx >> 7, c = idx & 127;
    float4 xr = ((const float4*)x)[n];
    float v = sb[c] + xr.x * sW[c] + xr.y * sW[H + c] + xr.z * sW[2 * H + c] + xr.w * sW[3 * H + c];
    g_h[idx] = fmaxf(v, 0.0f);
}

__global__ void k_zero_agg() {
    int i = blockIdx.x * blockDim.x + threadIdx.x;
    if (i < N_NODES * H) g_agg[i] = 0.0f;
}

// ---------------- edge MLP on mma.sync bf16 (hi/lo x3) ----------------
#define A_STR 68
#define B_STR 20
#define F_AH 0
#define F_AL (128 * A_STR)
#define F_BH (2 * 128 * A_STR)
#define F_BL (F_BH + 128 * B_STR)
#define F_META (F_BL + 128 * B_STR)
#define EDGE_SMEM ((F_META + 512) * 4)

__global__ __launch_bounds__(256, 2)
void k_edge_tc(const int* __restrict__ edge_index,
               const float* __restrict__ b1, const float* __restrict__ b2, int l) {
    extern __shared__ uint32_t smw[];
    uint32_t* sAh = smw + F_AH;
    uint32_t* sAl = smw + F_AL;
    uint32_t* sBh = smw + F_BH;
    uint32_t* sBl = smw + F_BL;
    int*   sSrc = (int*)(smw + F_META);
    int*   sDst = sSrc + 128;
    float* sB1  = (float*)(sDst + 128);
    float* sB2  = sB1 + 128;

    int tid = threadIdx.x;
    int w = tid >> 5, lane = tid & 31;
    int gid = lane >> 2, tig = lane & 3;

    int cnt0 = g_cnt[0];
    int nb0 = (cnt0 + TILE_E - 1) / TILE_E;
    int type, start, cnt, permBase;
    if ((int)blockIdx.x < nb0) {
        type = 0; start = blockIdx.x * TILE_E; cnt = cnt0; permBase = 0;
    } else {
        type = 1; start = ((int)blockIdx.x - nb0) * TILE_E;
        cnt = N_EDGESC - cnt0; permBase = cnt0;
        if (start >= cnt) return;
    }
    int lt = l * NT + type;

    if (tid < 128) {
        int g = start + tid; int s = -1, d = -1;
        if (g < cnt) { int e = g_perm[permBase + g]; s = edge_index[e]; d = edge_index[N_EDGESC + e]; }
        sSrc[tid] = s;
        sDst[tid] = d;
    } else {
        int c = tid - 128;
        sB1[c] = b1[lt * H + c];
        sB2[c] = b2[lt * H + c];
    }
    __syncthreads();

    float acc[16][4];
#pragma unroll
    for (int j = 0; j < 16; ++j)
#pragma unroll
        for (int q = 0; q < 4; ++q) acc[j][q] = 0.f;

    int rA0 = w * 16 + gid;
    int rA1 = rA0 + 8;

    // ===== GEMM1: cat[128x256] @ W1[256x128], 8 K-chunks of 32 =====
    const uint32_t* w1h = g_W1B_hi + (size_t)lt * 16384;
    const uint32_t* w1l = g_W1B_lo + (size_t)lt * 16384;
    for (int kc = 0; kc < 8; ++kc) {
        for (int i = tid; i < 1024; i += 256) {
            int r = i >> 3, q = i & 7;
            int node = (kc < 4) ? sSrc[r] : sDst[r];
            float4 v = make_float4(0.f, 0.f, 0.f, 0.f);
            if (node >= 0) v = *(const float4*)(g_h + (size_t)node * H + (kc & 3) * 32 + q * 4);
            uint32_t h0, l0, h1, l1;
            split_pack(v.x, v.y, h0, l0);
            split_pack(v.z, v.w, h1, l1);
            *(uint2*)(sAh + r * A_STR + q * 2) = make_uint2(h0, h1);
            *(uint2*)(sAl + r * A_STR + q * 2) = make_uint2(l0, l1);
        }
        {
            int n = tid >> 1, off = (tid & 1) * 8;
            const uint4* sh = (const uint4*)(w1h + n * 128 + kc * 16 + off);
            const uint4* sl = (const uint4*)(w1l + n * 128 + kc * 16 + off);
            *(uint4*)(sBh + n * B_STR + off)     = sh[0];
            *(uint4*)(sBh + n * B_STR + off + 4) = sh[1];
            *(uint4*)(sBl + n * B_STR + off)     = sl[0];
            *(uint4*)(sBl + n * B_STR + off + 4) = sl[1];
        }
        __syncthreads();
#pragma unroll
        for (int s = 0; s < 2; ++s) {
            int kwb = 8 * s;
            uint32_t ah0 = sAh[rA0 * A_STR + kwb + tig];
            uint32_t ah1 = sAh[rA1 * A_STR + kwb + tig];
            uint32_t ah2 = sAh[rA0 * A_STR + kwb + tig + 4];
            uint32_t ah3 = sAh[rA1 * A_STR + kwb + tig + 4];
            uint32_t al0 = sAl[rA0 * A_STR + kwb + tig];
            uint32_t al1 = sAl[rA1 * A_STR + kwb + tig];
            uint32_t al2 = sAl[rA0 * A_STR + kwb + tig + 4];
            uint32_t al3 = sAl[rA1 * A_STR + kwb + tig + 4];
#pragma unroll
            for (int j = 0; j < 16; ++j) {
                int nb = (j * 8 + gid) * B_STR + kwb + tig;
                uint32_t bh0 = sBh[nb], bh1 = sBh[nb + 4];
                uint32_t bl0 = sBl[nb], bl1 = sBl[nb + 4];
                mma_bf16(acc[j], ah0, ah1, ah2, ah3, bh0, bh1);
                mma_bf16(acc[j], al0, al1, al2, al3, bh0, bh1);
                mma_bf16(acc[j], ah0, ah1, ah2, ah3, bl0, bl1);
            }
        }
        __syncthreads();
    }

    // epilogue1: hidden = relu(acc + b1), pack to bf16 hi/lo in sAh/sAl
#pragma unroll
    for (int j = 0; j < 16; ++j) {
        int col = j * 8 + 2 * tig;
        float ba = sB1[col], bb = sB1[col + 1];
        float v0x = fmaxf(acc[j][0] + ba, 0.f), v0y = fmaxf(acc[j][1] + bb, 0.f);
        float v1x = fmaxf(acc[j][2] + ba, 0.f), v1y = fmaxf(acc[j][3] + bb, 0.f);
        int kw = j * 4 + tig;
        uint32_t h, lo;
        split_pack(v0x, v0y, h, lo);
        sAh[rA0 * A_STR + kw] = h; sAl[rA0 * A_STR + kw] = lo;
        split_pack(v1x, v1y, h, lo);
        sAh[rA1 * A_STR + kw] = h; sAl[rA1 * A_STR + kw] = lo;
        acc[j][0] = acc[j][1] = acc[j][2] = acc[j][3] = 0.f;
    }

    // ===== GEMM2: hidden[128x128] @ W2[128x128], 4 K-chunks of 32 =====
    const uint32_t* w2h = g_W2B_hi + (size_t)lt * 8192;
    const uint32_t* w2l = g_W2B_lo + (size_t)lt * 8192;
    for (int kc = 0; kc < 4; ++kc) {
        {
            int n = tid >> 1, off = (tid & 1) * 8;
            const uint4* sh = (const uint4*)(w2h + n * 64 + kc * 16 + off);
            const uint4* sl = (const uint4*)(w2l + n * 64 + kc * 16 + off);
            *(uint4*)(sBh + n * B_STR + off)     = sh[0];
            *(uint4*)(sBh + n * B_STR + off + 4) = sh[1];
            *(uint4*)(sBl + n * B_STR + off)     = sl[0];
            *(uint4*)(sBl + n * B_STR + off + 4) = sl[1];
        }
        __syncthreads();
#pragma unroll
        for (int s = 0; s < 2; ++s) {
            int kwb = kc * 16 + 8 * s;
            uint32_t ah0 = sAh[rA0 * A_STR + kwb + tig];
            uint32_t ah1 = sAh[rA1 * A_STR + kwb + tig];
            uint32_t ah2 = sAh[rA0 * A_STR + kwb + tig + 4];
            uint32_t ah3 = sAh[rA1 * A_STR + kwb + tig + 4];
            uint32_t al0 = sAl[rA0 * A_STR + kwb + tig];
            uint32_t al1 = sAl[rA1 * A_STR + kwb + tig];
            uint32_t al2 = sAl[rA0 * A_STR + kwb + tig + 4];
            uint32_t al3 = sAl[rA1 * A_STR + kwb + tig + 4];
#pragma unroll
            for (int j = 0; j < 16; ++j) {
                int nb = (j * 8 + gid) * B_STR + 8 * s + tig;
                uint32_t bh0 = sBh[nb], bh1 = sBh[nb + 4];
                uint32_t bl0 = sBl[nb], bl1 = sBl[nb + 4];
                mma_bf16(acc[j], ah0, ah1, ah2, ah3, bh0, bh1);
                mma_bf16(acc[j], al0, al1, al2, al3, bh0, bh1);
                mma_bf16(acc[j], ah0, ah1, ah2, ah3, bl0, bl1);
            }
        }
        __syncthreads();
    }

    // epilogue2: msgs = acc + b2 -> red into agg[dst]
    int d0 = sDst[rA0];
    int d1 = sDst[rA1];
#pragma unroll
    for (int j = 0; j < 16; ++j) {
        int col = j * 8 + 2 * tig;
        float ba = sB2[col], bb = sB2[col + 1];
        if (d0 >= 0) red2(g_agg + (size_t)d0 * H + col, acc[j][0] + ba, acc[j][1] + bb);
        if (d1 >= 0) red2(g_agg + (size_t)d1 * H + col, acc[j][2] + ba, acc[j][3] + bb);
    }
}

// ---------------- GRU GEMMs on mma.sync bf16 (hi/lo x3) ----------------
// block: 128 rows x 128 cols; grid (391, 3, 2); K=128 in 4 chunks of 32
#define A2_STR 20
#define G_AH 0
#define G_AL (128 * A2_STR)
#define G_BH (2 * 128 * A2_STR)
#define G_BL (G_BH + 128 * B_STR)
#define G_BIAS (G_BL + 128 * B_STR)
#define GRU_SMEM ((G_BIAS + 128) * 4)

__global__ __launch_bounds__(256)
void k_gru_tc(const float* __restrict__ bih, const float* __restrict__ bhh, int l) {
    extern __shared__ uint32_t smw[];
    uint32_t* sAh = smw + G_AH;
    uint32_t* sAl = smw + G_AL;
    uint32_t* sBh = smw + G_BH;
    uint32_t* sBl = smw + G_BL;
    float* sBias = (float*)(smw + G_BIAS);

    int tid = threadIdx.x;
    int w = tid >> 5, lane = tid & 31;
    int gid = lane >> 2, tig = lane & 3;

    int sel = blockIdx.z;
    const float* A = sel ? g_h : g_agg;
    float* C = sel ? g_gh : g_gi;
    const float* b = (sel ? bhh : bih) + l * 3 * H;
    const uint32_t* wbase_h = g_WGB_hi + ((size_t)sel * 3 + l) * 384 * 64;
    const uint32_t* wbase_l = g_WGB_lo + ((size_t)sel * 3 + l) * 384 * 64;

    int m0 = blockIdx.x * 128;
    int c0 = blockIdx.y * 128;

    if (tid < 128) sBias[tid] = b[c0 + tid];

    float acc[16][4];
#pragma unroll
    for (int j = 0; j < 16; ++j)
#pragma unroll
        for (int q = 0; q < 4; ++q) acc[j][q] = 0.f;

    int rA0 = w * 16 + gid;
    int rA1 = rA0 + 8;

    for (int kc = 0; kc < 4; ++kc) {
        // A chunk: rows m0..m0+127, k = kc*32..+31, split-pack
        for (int i = tid; i < 1024; i += 256) {
            int r = i >> 3, q = i & 7;
            int m = m0 + r;
            float4 v = make_float4(0.f, 0.f, 0.f, 0.f);
            if (m < N_NODES) v = *(const float4*)(A + (size_t)m * H + kc * 32 + q * 4);
            uint32_t h0, l0, h1, l1;
            split_pack(v.x, v.y, h0, l0);
            split_pack(v.z, v.w, h1, l1);
            *(uint2*)(sAh + r * A2_STR + q * 2) = make_uint2(h0, h1);
            *(uint2*)(sAl + r * A2_STR + q * 2) = make_uint2(l0, l1);
        }
        // B chunk: cols c0..c0+127, pre-packed
        {
            int n = tid >> 1, off = (tid & 1) * 8;
            const uint4* sh = (const uint4*)(wbase_h + (size_t)(c0 + n) * 64 + kc * 16 + off);
            const uint4* sl = (const uint4*)(wbase_l + (size_t)(c0 + n) * 64 + kc * 16 + off);
            *(uint4*)(sBh + n * B_STR + off)     = sh[0];
            *(uint4*)(sBh + n * B_STR + off + 4) = sh[1];
            *(uint4*)(sBl + n * B_STR + off)     = sl[0];
            *(uint4*)(sBl + n * B_STR + off + 4) = sl[1];
        }
        __syncthreads();
#pragma unroll
        for (int s = 0; s < 2; ++s) {
            int kwb = 8 * s;
            uint32_t ah0 = sAh[rA0 * A2_STR + kwb + tig];
            uint32_t ah1 = sAh[rA1 * A2_STR + kwb + tig];
            uint32_t ah2 = sAh[rA0 * A2_STR + kwb + tig + 4];
            uint32_t ah3 = sAh[rA1 * A2_STR + kwb + tig + 4];
            uint32_t al0 = sAl[rA0 * A2_STR + kwb + tig];
            uint32_t al1 = sAl[rA1 * A2_STR + kwb + tig];
            uint32_t al2 = sAl[rA0 * A2_STR + kwb + tig + 4];
            uint32_t al3 = sAl[rA1 * A2_STR + kwb + tig + 4];
#pragma unroll
            for (int j = 0; j < 16; ++j) {
                int nb = (j * 8 + gid) * B_STR + kwb + tig;
                uint32_t bh0 = sBh[nb], bh1 = sBh[nb + 4];
                uint32_t bl0 = sBl[nb], bl1 = sBl[nb + 4];
                mma_bf16(acc[j], ah0, ah1, ah2, ah3, bh0, bh1);
                mma_bf16(acc[j], al0, al1, al2, al3, bh0, bh1);
                mma_bf16(acc[j], ah0, ah1, ah2, ah3, bl0, bl1);
            }
        }
        __syncthreads();
    }

    int mg0 = m0 + rA0;
    int mg1 = m0 + rA1;
#pragma unroll
    for (int j = 0; j < 16; ++j) {
        int col = j * 8 + 2 * tig;
        float ba = sBias[col], bb = sBias[col + 1];
        if (mg0 < N_NODES)
            *(float2*)(C + (size_t)mg0 * 384 + c0 + col) =
                make_float2(acc[j][0] + ba, acc[j][1] + bb);
        if (mg1 < N_NODES)
            *(float2*)(C + (size_t)mg1 * 384 + c0 + col) =
                make_float2(acc[j][2] + ba, acc[j][3] + bb);
    }
}

__global__ void k_gru_combine() {
    int idx = blockIdx.x * blockDim.x + threadIdx.x;
    if (idx >= N_NODES * H) return;
    int n = idx >> 7, c = idx & 127;
    const float* gi = g_gi + (size_t)n * 384;
    const float* gh = g_gh + (size_t)n * 384;
    float r = sigm(gi[c] + gh[c]);
    float z = sigm(gi[128 + c] + gh[128 + c]);
    float nn = tanhf(gi[256 + c] + r * gh[256 + c]);
    g_h[idx] = (1.0f - z) * nn + z * g_h[idx];
}

// ---------------- readout ----------------
__global__ __launch_bounds__(256)
void k_readout(const float* __restrict__ Wr1, const float* __restrict__ br1,
               const float* __restrict__ Wr2, const float* __restrict__ br2,
               float* __restrict__ out, int nd) {
    extern __shared__ float smemf[];
    float* sW1 = smemf;
    float* sb1 = sW1 + H * H;
    float* sW2 = sb1 + H;
    float* sHrow = sW2 + H;

    for (int t = threadIdx.x; t < (H * H) / 4; t += blockDim.x)
        ((float4*)sW1)[t] = ((const float4*)Wr1)[t];
    if (threadIdx.x < H) {
        sb1[threadIdx.x] = br1[threadIdx.x];
        sW2[threadIdx.x] = Wr2[threadIdx.x];
    }
    __syncthreads();

    int w = threadIdx.x >> 5, lane = threadIdx.x & 31;
    float* myrow = sHrow + w * H;
    float b2v = br2[0];

    for (int n = blockIdx.x * 8 + w; n < nd; n += gridDim.x * 8) {
        ((float4*)myrow)[lane] = ((const float4*)(g_h + (size_t)n * H))[lane];
        __syncwarp();
        float hid0 = 0.f, hid1 = 0.f, hid2 = 0.f, hid3 = 0.f;
#pragma unroll 4
        for (int k = 0; k < H; ++k) {
            float a = myrow[k];
            float4 wv = ((const float4*)sW1)[k * 32 + lane];
            hid0 += a * wv.x; hid1 += a * wv.y; hid2 += a * wv.z; hid3 += a * wv.w;
        }
        float4 w2 = ((const float4*)sW2)[lane];
        float p = fmaxf(hid0 + sb1[lane * 4 + 0], 0.f) * w2.x
                + fmaxf(hid1 + sb1[lane * 4 + 1], 0.f) * w2.y
                + fmaxf(hid2 + sb1[lane * 4 + 2], 0.f) * w2.z
                + fmaxf(hid3 + sb1[lane * 4 + 3], 0.f) * w2.w;
#pragma unroll
        for (int o = 16; o > 0; o >>= 1) p += __shfl_down_sync(0xffffffffu, p, o);
        if (lane == 0) out[n] = p + b2v;
        __syncwarp();
    }
}

// ---------------- launch ----------------
extern "C" void kernel_launch(void* const* d_in, const int* in_sizes, int n_in,
                              void* d_out, int out_size) {
    int base = (n_in >= 18) ? 4 : 3;
    const float* x          = (const float*)d_in[0];
    const int*   edge_index = (const int*)d_in[1];
    const int*   edge_type  = (const int*)d_in[2];
    const float* W_in = (const float*)d_in[base + 0];
    const float* b_in = (const float*)d_in[base + 1];
    const float* W1   = (const float*)d_in[base + 2];
    const float* b1   = (const float*)d_in[base + 3];
    const float* W2   = (const float*)d_in[base + 4];
    const float* b2   = (const float*)d_in[base + 5];
    const float* W_ih = (const float*)d_in[base + 6];
    const float* b_ih = (const float*)d_in[base + 7];
    const float* W_hh = (const float*)d_in[base + 8];
    const float* b_hh = (const float*)d_in[base + 9];
    const float* Wr1  = (const float*)d_in[base + 10];
    const float* br1  = (const float*)d_in[base + 11];
    const float* Wr2  = (const float*)d_in[base + 12];
    const float* br2  = (const float*)d_in[base + 13];
    float* out = (float*)d_out;

    const int READ_SMEM = (128 * 128 + 128 + 128 + 8 * 128) * 4;
    cudaFuncSetAttribute(k_edge_tc, cudaFuncAttributeMaxDynamicSharedMemorySize, EDGE_SMEM);
    cudaFuncSetAttribute(k_gru_tc,  cudaFuncAttributeMaxDynamicSharedMemorySize, GRU_SMEM);
    cudaFuncSetAttribute(k_readout, cudaFuncAttributeMaxDynamicSharedMemorySize, READ_SMEM);

    k_zero_cnt<<<1, 32>>>();
    k_count<<<(N_EDGESC + 255) / 256, 256>>>(edge_type);
    k_seed<<<1, 1>>>();
    k_scatter<<<(N_EDGESC + 255) / 256, 256>>>(edge_type);

    const int NPW = 6 * 128 * 128 + 6 * 128 * 64;
    k_prep_w<<<(NPW + 255) / 256, 256>>>(W1, W2);
    k_prep_gru<<<(2 * 3 * 384 * 64 + 255) / 256, 256>>>(W_ih, W_hh);
    k_init<<<(N_NODES * H + 255) / 256, 256>>>(x, W_in, b_in);

    const int NEL = N_NODES * H;
    const int EDGE_BLOCKS = N_EDGESC / TILE_E + 2;
    for (int l = 0; l < 3; ++l) {
        k_zero_agg<<<(NEL + 255) / 256, 256>>>();
        k_edge_tc<<<EDGE_BLOCKS, 256, EDGE_SMEM>>>(edge_index, b1, b2, l);
        dim3 gg((N_NODES + 127) / 128, 3, 2);
        k_gru_tc<<<gg, 256, GRU_SMEM>>>(b_ih, b_hh, l);
        k_gru_combine<<<(NEL + 255) / 256, 256>>>();
    }

    k_readout<<<625, 256, READ_SMEM>>>(Wr1, br1, Wr2, br2, out, out_size);
}

// round 13
// speedup vs baseline: 3.3102x; 1.2120x over previous
#include <cuda_runtime.h>
#include <cuda_bf16.h>
#include <math.h>
#include <stdint.h>

#define N_NODES 50000
#define N_EDGESC 400000
#define H 128
#define NT 2
#define FEAT 4
#define TILE_E 128

// ---------------- device scratch (no runtime allocation) ----------------
__device__ float g_h[N_NODES * H];
__device__ float g_agg[N_NODES * H];
__device__ float g_gi[N_NODES * 3 * H];
__device__ float g_gh[N_NODES * 3 * H];
__device__ int   g_perm[N_EDGESC];
__device__ int   g_cnt[2];
__device__ int   g_cursor[2];
// transposed, bf16 hi/lo packed weights: word [lt][n][kw] holds bf16(k=2kw), bf16(k=2kw+1)
__device__ uint32_t g_W1B_hi[6 * 128 * 128];
__device__ uint32_t g_W1B_lo[6 * 128 * 128];
__device__ uint32_t g_W2B_hi[6 * 128 * 64];
__device__ uint32_t g_W2B_lo[6 * 128 * 64];
// GRU weights: [sel(ih/hh)][l][n(384)][kw(64)]
__device__ uint32_t g_WGB_hi[2 * 3 * 384 * 64];
__device__ uint32_t g_WGB_lo[2 * 3 * 384 * 64];

__device__ __forceinline__ float sigm(float v) { return 1.0f / (1.0f + expf(-v)); }

__device__ __forceinline__ void split_pack(float x, float y, uint32_t& hi, uint32_t& lo) {
    __nv_bfloat162 h = __floats2bfloat162_rn(x, y);
    hi = reinterpret_cast<uint32_t&>(h);
    float rx = x - __low2float(h);
    float ry = y - __high2float(h);
    __nv_bfloat162 l = __floats2bfloat162_rn(rx, ry);
    lo = reinterpret_cast<uint32_t&>(l);
}

__device__ __forceinline__ void mma_bf16(float* c, uint32_t a0, uint32_t a1, uint32_t a2,
                                         uint32_t a3, uint32_t b0, uint32_t b1) {
    asm volatile(
        "mma.sync.aligned.m16n8k16.row.col.f32.bf16.bf16.f32 "
        "{%0,%1,%2,%3}, {%4,%5,%6,%7}, {%8,%9}, {%0,%1,%2,%3};"
        : "+f"(c[0]), "+f"(c[1]), "+f"(c[2]), "+f"(c[3])
        : "r"(a0), "r"(a1), "r"(a2), "r"(a3), "r"(b0), "r"(b1));
}

__device__ __forceinline__ void red2(float* p, float a, float b) {
    asm volatile("red.global.add.v2.f32 [%0], {%1, %2};" :: "l"(p), "f"(a), "f"(b) : "memory");
}

__device__ __forceinline__ void cp16(uint32_t saddr, const void* g) {
    asm volatile("cp.async.cg.shared.global [%0], [%1], 16;" :: "r"(saddr), "l"(g));
}
#define CP_COMMIT() asm volatile("cp.async.commit_group;" ::: "memory")
#define CP_WAIT0()  asm volatile("cp.async.wait_group 0;" ::: "memory")
#define CP_WAIT1()  asm volatile("cp.async.wait_group 1;" ::: "memory")

__device__ __forceinline__ uint32_t smem_u32(const void* p) {
    uint32_t a;
    asm("{ .reg .u64 t; cvta.to.shared.u64 t, %1; cvt.u32.u64 %0, t; }" : "=r"(a) : "l"(p));
    return a;
}

// ---------------- edge partition by type ----------------
__global__ void k_zero_cnt() { if (threadIdx.x < 2) g_cnt[threadIdx.x] = 0; }

__global__ void k_count(const int* __restrict__ et) {
    __shared__ int lc[2];
    if (threadIdx.x < 2) lc[threadIdx.x] = 0;
    __syncthreads();
    int e = blockIdx.x * blockDim.x + threadIdx.x;
    if (e < N_EDGESC) atomicAdd(&lc[et[e]], 1);
    __syncthreads();
    if (threadIdx.x < 2) atomicAdd(&g_cnt[threadIdx.x], lc[threadIdx.x]);
}

__global__ void k_seed() { g_cursor[0] = 0; g_cursor[1] = g_cnt[0]; }

__global__ void k_scatter(const int* __restrict__ et) {
    __shared__ int lc[2];
    __shared__ int base[2];
    if (threadIdx.x < 2) lc[threadIdx.x] = 0;
    __syncthreads();
    int e = blockIdx.x * blockDim.x + threadIdx.x;
    int t = 0, rank = 0;
    bool valid = (e < N_EDGESC);
    if (valid) { t = et[e]; rank = atomicAdd(&lc[t], 1); }
    __syncthreads();
    if (threadIdx.x < 2) base[threadIdx.x] = atomicAdd(&g_cursor[threadIdx.x], lc[threadIdx.x]);
    __syncthreads();
    if (valid) g_perm[base[t] + rank] = e;
}

// ---------------- weight transpose + bf16 split-pack (once per launch) ----------------
__global__ void k_prep_w(const float* __restrict__ W1, const float* __restrict__ W2) {
    int idx = blockIdx.x * blockDim.x + threadIdx.x;
    const int NW1 = 6 * 128 * 128;
    const int NW2 = 6 * 128 * 64;
    if (idx < NW1) {
        int lt = idx >> 14, rem = idx & 16383;
        int n = rem >> 7, kw = rem & 127;
        const float* base = W1 + (size_t)lt * 32768;
        float v0 = base[(2 * kw) * 128 + n];
        float v1 = base[(2 * kw + 1) * 128 + n];
        uint32_t hi, lo;
        split_pack(v0, v1, hi, lo);
        int o = lt * 16384 + n * 128 + kw;
        g_W1B_hi[o] = hi; g_W1B_lo[o] = lo;
    } else if (idx < NW1 + NW2) {
        int i2 = idx - NW1;
        int lt = i2 >> 13, rem = i2 & 8191;
        int n = rem >> 6, kw = rem & 63;
        const float* base = W2 + (size_t)lt * 16384;
        float v0 = base[(2 * kw) * 128 + n];
        float v1 = base[(2 * kw + 1) * 128 + n];
        uint32_t hi, lo;
        split_pack(v0, v1, hi, lo);
        int o = lt * 8192 + n * 64 + kw;
        g_W2B_hi[o] = hi; g_W2B_lo[o] = lo;
    }
}

__global__ void k_prep_gru(const float* __restrict__ Wih, const float* __restrict__ Whh) {
    int idx = blockIdx.x * blockDim.x + threadIdx.x;
    const int TOT = 2 * 3 * 384 * 64;
    if (idx >= TOT) return;
    int sel = idx / 73728, rem = idx % 73728;
    int l = rem / 24576, rem2 = rem % 24576;
    int n = rem2 >> 6, kw = rem2 & 63;
    const float* src = (sel ? Whh : Wih) + (size_t)l * H * 3 * H;
    float v0 = src[(2 * kw) * 384 + n];
    float v1 = src[(2 * kw + 1) * 384 + n];
    uint32_t hi, lo;
    split_pack(v0, v1, hi, lo);
    g_WGB_hi[idx] = hi;
    g_WGB_lo[idx] = lo;
}

// ---------------- h = relu(x @ W_in + b_in) ----------------
__global__ void k_init(const float* __restrict__ x, const float* __restrict__ Win,
                       const float* __restrict__ bin) {
    __shared__ float sW[FEAT * H];
    __shared__ float sb[H];
    for (int i = threadIdx.x; i < FEAT * H; i += blockDim.x) sW[i] = Win[i];
    if (threadIdx.x < H) sb[threadIdx.x] = bin[threadIdx.x];
    __syncthreads();
    int idx = blockIdx.x * blockDim.x + threadIdx.x;
    if (idx >= N_NODES * H) return;
    int n = idx >> 7, c = idx & 127;
    float4 xr = ((const float4*)x)[n];
    float v = sb[c] + xr.x * sW[c] + xr.y * sW[H + c] + xr.z * sW[2 * H + c] + xr.w * sW[3 * H + c];
    g_h[idx] = fmaxf(v, 0.0f);
}

__global__ void k_zero_agg() {
    int i = blockIdx.x * blockDim.x + threadIdx.x;
    if (i < N_NODES * H) g_agg[i] = 0.0f;
}

// ---------------- edge MLP: bf16 hi/lo x3, pipelined staging ----------------
// words: sAh [128][68] (chunk staging kw0..15 + hidden kw0..63), sAl same
//        B: 2 bufs x (hi[128][20] + lo[128][20])
#define A_STR 68
#define B_STR 20
#define F_AH 0
#define F_AL (128 * A_STR)
#define F_B  (2 * 128 * A_STR)
#define B_BUF_W (2 * 128 * B_STR)
#define F_META (F_B + 2 * B_BUF_W)
#define EDGE_SMEM ((F_META + 512) * 4)

__global__ __launch_bounds__(256, 2)
void k_edge_tc(const int* __restrict__ edge_index,
               const float* __restrict__ b1, const float* __restrict__ b2, int l) {
    extern __shared__ uint32_t smw[];
    uint32_t* sAh = smw + F_AH;
    uint32_t* sAl = smw + F_AL;
    int*   sSrc = (int*)(smw + F_META);
    int*   sDst = sSrc + 128;
    float* sB1  = (float*)(sDst + 128);
    float* sB2  = sB1 + 128;
    const uint32_t su = smem_u32(smw);

    int tid = threadIdx.x;
    int w = tid >> 5, lane = tid & 31;
    int gid = lane >> 2, tig = lane & 3;

    int cnt0 = g_cnt[0];
    int nb0 = (cnt0 + TILE_E - 1) / TILE_E;
    int type, start, cnt, permBase;
    if ((int)blockIdx.x < nb0) {
        type = 0; start = blockIdx.x * TILE_E; cnt = cnt0; permBase = 0;
    } else {
        type = 1; start = ((int)blockIdx.x - nb0) * TILE_E;
        cnt = N_EDGESC - cnt0; permBase = cnt0;
        if (start >= cnt) return;
    }
    int lt = l * NT + type;

    const uint32_t* w1h = g_W1B_hi + (size_t)lt * 16384;
    const uint32_t* w1l = g_W1B_lo + (size_t)lt * 16384;
    const uint32_t* w2h = g_W2B_hi + (size_t)lt * 8192;
    const uint32_t* w2l = g_W2B_lo + (size_t)lt * 8192;

    int nB = tid >> 1, offB = (tid & 1) * 8;

    // issue B(0) immediately (buf 0)
    {
        uint32_t dst = su + (F_B + nB * B_STR + offB) * 4;
        const uint32_t* gh_ = w1h + nB * 128 + offB;
        const uint32_t* gl_ = w1l + nB * 128 + offB;
        cp16(dst, gh_); cp16(dst + 16, gh_ + 4);
        cp16(dst + 128 * B_STR * 4, gl_); cp16(dst + 128 * B_STR * 4 + 16, gl_ + 4);
        CP_COMMIT();
    }

    if (tid < 128) {
        int g = start + tid; int s = -1, d = -1;
        if (g < cnt) { int e = g_perm[permBase + g]; s = edge_index[e]; d = edge_index[N_EDGESC + e]; }
        sSrc[tid] = s;
        sDst[tid] = d;
    } else {
        int c = tid - 128;
        sB1[c] = b1[lt * H + c];
        sB2[c] = b2[lt * H + c];
    }
    __syncthreads();

    float acc[16][4];
#pragma unroll
    for (int j = 0; j < 16; ++j)
#pragma unroll
        for (int q = 0; q < 4; ++q) acc[j][q] = 0.f;

    int rA0 = w * 16 + gid;
    int rA1 = rA0 + 8;

    // prefetch A chunk 0
    float4 aCur[4], aNxt[4];
#pragma unroll
    for (int i = 0; i < 4; ++i) {
        int i0 = tid + i * 256, r = i0 >> 3, q = i0 & 7;
        int node = sSrc[r];
        aCur[i] = (node >= 0) ? *(const float4*)(g_h + (size_t)node * H + q * 4)
                              : make_float4(0.f, 0.f, 0.f, 0.f);
    }

    // ===== GEMM1: 8 K-chunks =====
    for (int kc = 0; kc < 8; ++kc) {
        int buf = kc & 1;
        // store A(kc) from regs
#pragma unroll
        for (int i = 0; i < 4; ++i) {
            int i0 = tid + i * 256, r = i0 >> 3, q = i0 & 7;
            uint32_t h0, l0, h1, l1;
            split_pack(aCur[i].x, aCur[i].y, h0, l0);
            split_pack(aCur[i].z, aCur[i].w, h1, l1);
            *(uint2*)(sAh + r * A_STR + q * 2) = make_uint2(h0, h1);
            *(uint2*)(sAl + r * A_STR + q * 2) = make_uint2(l0, l1);
        }
        if (kc < 7) {
            int kn = kc + 1;
            // prefetch A(kc+1)
#pragma unroll
            for (int i = 0; i < 4; ++i) {
                int i0 = tid + i * 256, r = i0 >> 3, q = i0 & 7;
                int node = (kn < 4) ? sSrc[r] : sDst[r];
                aNxt[i] = (node >= 0)
                    ? *(const float4*)(g_h + (size_t)node * H + (kn & 3) * 32 + q * 4)
                    : make_float4(0.f, 0.f, 0.f, 0.f);
            }
            // issue B(kc+1) into buf^1
            uint32_t dst = su + (F_B + (buf ^ 1) * B_BUF_W + nB * B_STR + offB) * 4;
            const uint32_t* gh_ = w1h + nB * 128 + kn * 16 + offB;
            const uint32_t* gl_ = w1l + nB * 128 + kn * 16 + offB;
            cp16(dst, gh_); cp16(dst + 16, gh_ + 4);
            cp16(dst + 128 * B_STR * 4, gl_); cp16(dst + 128 * B_STR * 4 + 16, gl_ + 4);
            CP_COMMIT();
            CP_WAIT1();
        } else {
            CP_WAIT0();
        }
        __syncthreads();
        const uint32_t* sBh = smw + F_B + buf * B_BUF_W;
        const uint32_t* sBl = sBh + 128 * B_STR;
#pragma unroll
        for (int s = 0; s < 2; ++s) {
            int kwb = 8 * s;
            uint32_t ah0 = sAh[rA0 * A_STR + kwb + tig];
            uint32_t ah1 = sAh[rA1 * A_STR + kwb + tig];
            uint32_t ah2 = sAh[rA0 * A_STR + kwb + tig + 4];
            uint32_t ah3 = sAh[rA1 * A_STR + kwb + tig + 4];
            uint32_t al0 = sAl[rA0 * A_STR + kwb + tig];
            uint32_t al1 = sAl[rA1 * A_STR + kwb + tig];
            uint32_t al2 = sAl[rA0 * A_STR + kwb + tig + 4];
            uint32_t al3 = sAl[rA1 * A_STR + kwb + tig + 4];
#pragma unroll
            for (int j = 0; j < 16; ++j) {
                int nb = (j * 8 + gid) * B_STR + kwb + tig;
                uint32_t bh0 = sBh[nb], bh1 = sBh[nb + 4];
                uint32_t bl0 = sBl[nb], bl1 = sBl[nb + 4];
                mma_bf16(acc[j], ah0, ah1, ah2, ah3, bh0, bh1);
                mma_bf16(acc[j], al0, al1, al2, al3, bh0, bh1);
                mma_bf16(acc[j], ah0, ah1, ah2, ah3, bl0, bl1);
            }
        }
        __syncthreads();
#pragma unroll
        for (int i = 0; i < 4; ++i) aCur[i] = aNxt[i];
    }

    // issue B2(0) into buf 0 (buf0 free: last read at GEMM1 kc=6)
    {
        uint32_t dst = su + (F_B + nB * B_STR + offB) * 4;
        const uint32_t* gh_ = w2h + nB * 64 + offB;
        const uint32_t* gl_ = w2l + nB * 64 + offB;
        cp16(dst, gh_); cp16(dst + 16, gh_ + 4);
        cp16(dst + 128 * B_STR * 4, gl_); cp16(dst + 128 * B_STR * 4 + 16, gl_ + 4);
        CP_COMMIT();
    }

    // epilogue1: hidden = relu(acc + b1) -> same-thread smem slots
#pragma unroll
    for (int j = 0; j < 16; ++j) {
        int col = j * 8 + 2 * tig;
        float ba = sB1[col], bb = sB1[col + 1];
        float v0x = fmaxf(acc[j][0] + ba, 0.f), v0y = fmaxf(acc[j][1] + bb, 0.f);
        float v1x = fmaxf(acc[j][2] + ba, 0.f), v1y = fmaxf(acc[j][3] + bb, 0.f);
        int kw = j * 4 + tig;
        uint32_t h, lo;
        split_pack(v0x, v0y, h, lo);
        sAh[rA0 * A_STR + kw] = h; sAl[rA0 * A_STR + kw] = lo;
        split_pack(v1x, v1y, h, lo);
        sAh[rA1 * A_STR + kw] = h; sAl[rA1 * A_STR + kw] = lo;
        acc[j][0] = acc[j][1] = acc[j][2] = acc[j][3] = 0.f;
    }

    // ===== GEMM2: 4 K-chunks =====
    for (int kc = 0; kc < 4; ++kc) {
        int buf = kc & 1;
        if (kc < 3) {
            int kn = kc + 1;
            uint32_t dst = su + (F_B + (buf ^ 1) * B_BUF_W + nB * B_STR + offB) * 4;
            const uint32_t* gh_ = w2h + nB * 64 + kn * 16 + offB;
            const uint32_t* gl_ = w2l + nB * 64 + kn * 16 + offB;
            cp16(dst, gh_); cp16(dst + 16, gh_ + 4);
            cp16(dst + 128 * B_STR * 4, gl_); cp16(dst + 128 * B_STR * 4 + 16, gl_ + 4);
            CP_COMMIT();
            CP_WAIT1();
        } else {
            CP_WAIT0();
        }
        __syncthreads();
        const uint32_t* sBh = smw + F_B + buf * B_BUF_W;
        const uint32_t* sBl = sBh + 128 * B_STR;
#pragma unroll
        for (int s = 0; s < 2; ++s) {
            int kwb = kc * 16 + 8 * s;
            uint32_t ah0 = sAh[rA0 * A_STR + kwb + tig];
            uint32_t ah1 = sAh[rA1 * A_STR + kwb + tig];
            uint32_t ah2 = sAh[rA0 * A_STR + kwb + tig + 4];
            uint32_t ah3 = sAh[rA1 * A_STR + kwb + tig + 4];
            uint32_t al0 = sAl[rA0 * A_STR + kwb + tig];
            uint32_t al1 = sAl[rA1 * A_STR + kwb + tig];
            uint32_t al2 = sAl[rA0 * A_STR + kwb + tig + 4];
            uint32_t al3 = sAl[rA1 * A_STR + kwb + tig + 4];
#pragma unroll
            for (int j = 0; j < 16; ++j) {
                int nb = (j * 8 + gid) * B_STR + 8 * s + tig;
                uint32_t bh0 = sBh[nb], bh1 = sBh[nb + 4];
                uint32_t bl0 = sBl[nb], bl1 = sBl[nb + 4];
                mma_bf16(acc[j], ah0, ah1, ah2, ah3, bh0, bh1);
                mma_bf16(acc[j], al0, al1, al2, al3, bh0, bh1);
                mma_bf16(acc[j], ah0, ah1, ah2, ah3, bl0, bl1);
            }
        }
        __syncthreads();
    }

    // epilogue2: msgs = acc + b2 -> red into agg[dst]
    int d0 = sDst[rA0];
    int d1 = sDst[rA1];
#pragma unroll
    for (int j = 0; j < 16; ++j) {
        int col = j * 8 + 2 * tig;
        float ba = sB2[col], bb = sB2[col + 1];
        if (d0 >= 0) red2(g_agg + (size_t)d0 * H + col, acc[j][0] + ba, acc[j][1] + bb);
        if (d1 >= 0) red2(g_agg + (size_t)d1 * H + col, acc[j][2] + ba, acc[j][3] + bb);
    }
}

// ---------------- GRU GEMMs: bf16 hi/lo x3, pipelined ----------------
#define A2_STR 20
#define G_AH 0
#define G_AL (128 * A2_STR)
#define G_B  (2 * 128 * A2_STR)
#define GB_BUF_W (2 * 128 * B_STR)
#define G_BIAS (G_B + 2 * GB_BUF_W)
#define GRU_SMEM ((G_BIAS + 128) * 4)

__global__ __launch_bounds__(256, 2)
void k_gru_tc(const float* __restrict__ bih, const float* __restrict__ bhh, int l) {
    extern __shared__ uint32_t smw[];
    uint32_t* sAh = smw + G_AH;
    uint32_t* sAl = smw + G_AL;
    float* sBias = (float*)(smw + G_BIAS);
    const uint32_t su = smem_u32(smw);

    int tid = threadIdx.x;
    int w = tid >> 5, lane = tid & 31;
    int gid = lane >> 2, tig = lane & 3;

    int sel = blockIdx.z;
    const float* A = sel ? g_h : g_agg;
    float* C = sel ? g_gh : g_gi;
    const float* b = (sel ? bhh : bih) + l * 3 * H;
    const uint32_t* wbh = g_WGB_hi + ((size_t)sel * 3 + l) * 384 * 64;
    const uint32_t* wbl = g_WGB_lo + ((size_t)sel * 3 + l) * 384 * 64;

    int m0 = blockIdx.x * 128;
    int c0 = blockIdx.y * 128;

    int nB = tid >> 1, offB = (tid & 1) * 8;

    // issue B(0) (buf 0)
    {
        uint32_t dst = su + (G_B + nB * B_STR + offB) * 4;
        const uint32_t* gh_ = wbh + (size_t)(c0 + nB) * 64 + offB;
        const uint32_t* gl_ = wbl + (size_t)(c0 + nB) * 64 + offB;
        cp16(dst, gh_); cp16(dst + 16, gh_ + 4);
        cp16(dst + 128 * B_STR * 4, gl_); cp16(dst + 128 * B_STR * 4 + 16, gl_ + 4);
        CP_COMMIT();
    }

    if (tid < 128) sBias[tid] = b[c0 + tid];

    float acc[16][4];
#pragma unroll
    for (int j = 0; j < 16; ++j)
#pragma unroll
        for (int q = 0; q < 4; ++q) acc[j][q] = 0.f;

    int rA0 = w * 16 + gid;
    int rA1 = rA0 + 8;

    // prefetch A(0)
    float4 aCur[4], aNxt[4];
#pragma unroll
    for (int i = 0; i < 4; ++i) {
        int i0 = tid + i * 256, r = i0 >> 3, q = i0 & 7;
        int m = m0 + r;
        aCur[i] = (m < N_NODES) ? *(const float4*)(A + (size_t)m * H + q * 4)
                                : make_float4(0.f, 0.f, 0.f, 0.f);
    }

    for (int kc = 0; kc < 4; ++kc) {
        int buf = kc & 1;
#pragma unroll
        for (int i = 0; i < 4; ++i) {
            int i0 = tid + i * 256, r = i0 >> 3, q = i0 & 7;
            uint32_t h0, l0, h1, l1;
            split_pack(aCur[i].x, aCur[i].y, h0, l0);
            split_pack(aCur[i].z, aCur[i].w, h1, l1);
            *(uint2*)(sAh + r * A2_STR + q * 2) = make_uint2(h0, h1);
            *(uint2*)(sAl + r * A2_STR + q * 2) = make_uint2(l0, l1);
        }
        if (kc < 3) {
            int kn = kc + 1;
#pragma unroll
            for (int i = 0; i < 4; ++i) {
                int i0 = tid + i * 256, r = i0 >> 3, q = i0 & 7;
                int m = m0 + r;
                aNxt[i] = (m < N_NODES)
                    ? *(const float4*)(A + (size_t)m * H + kn * 32 + q * 4)
                    : make_float4(0.f, 0.f, 0.f, 0.f);
            }
            uint32_t dst = su + (G_B + (buf ^ 1) * GB_BUF_W + nB * B_STR + offB) * 4;
            const uint32_t* gh_ = wbh + (size_t)(c0 + nB) * 64 + kn * 16 + offB;
            const uint32_t* gl_ = wbl + (size_t)(c0 + nB) * 64 + kn * 16 + offB;
            cp16(dst, gh_); cp16(dst + 16, gh_ + 4);
            cp16(dst + 128 * B_STR * 4, gl_); cp16(dst + 128 * B_STR * 4 + 16, gl_ + 4);
            CP_COMMIT();
            CP_WAIT1();
        } else {
            CP_WAIT0();
        }
        __syncthreads();
        const uint32_t* sBh = smw + G_B + buf * GB_BUF_W;
        const uint32_t* sBl = sBh + 128 * B_STR;
#pragma unroll
        for (int s = 0; s < 2; ++s) {
            int kwb = 8 * s;
            uint32_t ah0 = sAh[rA0 * A2_STR + kwb + tig];
            uint32_t ah1 = sAh[rA1 * A2_STR + kwb + tig];
            uint32_t ah2 = sAh[rA0 * A2_STR + kwb + tig + 4];
            uint32_t ah3 = sAh[rA1 * A2_STR + kwb + tig + 4];
            uint32_t al0 = sAl[rA0 * A2_STR + kwb + tig];
            uint32_t al1 = sAl[rA1 * A2_STR + kwb + tig];
            uint32_t al2 = sAl[rA0 * A2_STR + kwb + tig + 4];
            uint32_t al3 = sAl[rA1 * A2_STR + kwb + tig + 4];
#pragma unroll
            for (int j = 0; j < 16; ++j) {
                int nb = (j * 8 + gid) * B_STR + kwb + tig;
                uint32_t bh0 = sBh[nb], bh1 = sBh[nb + 4];
                uint32_t bl0 = sBl[nb], bl1 = sBl[nb + 4];
                mma_bf16(acc[j], ah0, ah1, ah2, ah3, bh0, bh1);
                mma_bf16(acc[j], al0, al1, al2, al3, bh0, bh1);
                mma_bf16(acc[j], ah0, ah1, ah2, ah3, bl0, bl1);
            }
        }
        __syncthreads();
#pragma unroll
        for (int i = 0; i < 4; ++i) aCur[i] = aNxt[i];
    }

    int mg0 = m0 + rA0;
    int mg1 = m0 + rA1;
#pragma unroll
    for (int j = 0; j < 16; ++j) {
        int col = j * 8 + 2 * tig;
        float ba = sBias[col], bb = sBias[col + 1];
        if (mg0 < N_NODES)
            *(float2*)(C + (size_t)mg0 * 384 + c0 + col) =
                make_float2(acc[j][0] + ba, acc[j][1] + bb);
        if (mg1 < N_NODES)
            *(float2*)(C + (size_t)mg1 * 384 + c0 + col) =
                make_float2(acc[j][2] + ba, acc[j][3] + bb);
    }
}

__global__ void k_gru_combine() {
    int idx = blockIdx.x * blockDim.x + threadIdx.x;
    if (idx >= N_NODES * H) return;
    int n = idx >> 7, c = idx & 127;
    const float* gi = g_gi + (size_t)n * 384;
    const float* gh = g_gh + (size_t)n * 384;
    float r = sigm(gi[c] + gh[c]);
    float z = sigm(gi[128 + c] + gh[128 + c]);
    float nn = tanhf(gi[256 + c] + r * gh[256 + c]);
    g_h[idx] = (1.0f - z) * nn + z * g_h[idx];
}

// ---------------- readout ----------------
__global__ __launch_bounds__(256)
void k_readout(const float* __restrict__ Wr1, const float* __restrict__ br1,
               const float* __restrict__ Wr2, const float* __restrict__ br2,
               float* __restrict__ out, int nd) {
    extern __shared__ float smemf[];
    float* sW1 = smemf;
    float* sb1 = sW1 + H * H;
    float* sW2 = sb1 + H;
    float* sHrow = sW2 + H;

    for (int t = threadIdx.x; t < (H * H) / 4; t += blockDim.x)
        ((float4*)sW1)[t] = ((const float4*)Wr1)[t];
    if (threadIdx.x < H) {
        sb1[threadIdx.x] = br1[threadIdx.x];
        sW2[threadIdx.x] = Wr2[threadIdx.x];
    }
    __syncthreads();

    int w = threadIdx.x >> 5, lane = threadIdx.x & 31;
    float* myrow = sHrow + w * H;
    float b2v = br2[0];

    for (int n = blockIdx.x * 8 + w; n < nd; n += gridDim.x * 8) {
        ((float4*)myrow)[lane] = ((const float4*)(g_h + (size_t)n * H))[lane];
        __syncwarp();
        float hid0 = 0.f, hid1 = 0.f, hid2 = 0.f, hid3 = 0.f;
#pragma unroll 4
        for (int k = 0; k < H; ++k) {
            float a = myrow[k];
            float4 wv = ((const float4*)sW1)[k * 32 + lane];
            hid0 += a * wv.x; hid1 += a * wv.y; hid2 += a * wv.z; hid3 += a * wv.w;
        }
        float4 w2 = ((const float4*)sW2)[lane];
        float p = fmaxf(hid0 + sb1[lane * 4 + 0], 0.f) * w2.x
                + fmaxf(hid1 + sb1[lane * 4 + 1], 0.f) * w2.y
                + fmaxf(hid2 + sb1[lane * 4 + 2], 0.f) * w2.z
                + fmaxf(hid3 + sb1[lane * 4 + 3], 0.f) * w2.w;
#pragma unroll
        for (int o = 16; o > 0; o >>= 1) p += __shfl_down_sync(0xffffffffu, p, o);
        if (lane == 0) out[n] = p + b2v;
        __syncwarp();
    }
}

// ---------------- launch ----------------
extern "C" void kernel_launch(void* const* d_in, const int* in_sizes, int n_in,
                              void* d_out, int out_size) {
    int base = (n_in >= 18) ? 4 : 3;
    const float* x          = (const float*)d_in[0];
    const int*   edge_index = (const int*)d_in[1];
    const int*   edge_type  = (const int*)d_in[2];
    const float* W_in = (const float*)d_in[base + 0];
    const float* b_in = (const float*)d_in[base + 1];
    const float* W1   = (const float*)d_in[base + 2];
    const float* b1   = (const float*)d_in[base + 3];
    const float* W2   = (const float*)d_in[base + 4];
    const float* b2   = (const float*)d_in[base + 5];
    const float* W_ih = (const float*)d_in[base + 6];
    const float* b_ih = (const float*)d_in[base + 7];
    const float* W_hh = (const float*)d_in[base + 8];
    const float* b_hh = (const float*)d_in[base + 9];
    const float* Wr1  = (const float*)d_in[base + 10];
    const float* br1  = (const float*)d_in[base + 11];
    const float* Wr2  = (const float*)d_in[base + 12];
    const float* br2  = (const float*)d_in[base + 13];
    float* out = (float*)d_out;

    const int READ_SMEM = (128 * 128 + 128 + 128 + 8 * 128) * 4;
    cudaFuncSetAttribute(k_edge_tc, cudaFuncAttributeMaxDynamicSharedMemorySize, EDGE_SMEM);
    cudaFuncSetAttribute(k_gru_tc,  cudaFuncAttributeMaxDynamicSharedMemorySize, GRU_SMEM);
    cudaFuncSetAttribute(k_readout, cudaFuncAttributeMaxDynamicSharedMemorySize, READ_SMEM);

    k_zero_cnt<<<1, 32>>>();
    k_count<<<(N_EDGESC + 255) / 256, 256>>>(edge_type);
    k_seed<<<1, 1>>>();
    k_scatter<<<(N_EDGESC + 255) / 256, 256>>>(edge_type);

    const int NPW = 6 * 128 * 128 + 6 * 128 * 64;
    k_prep_w<<<(NPW + 255) / 256, 256>>>(W1, W2);
    k_prep_gru<<<(2 * 3 * 384 * 64 + 255) / 256, 256>>>(W_ih, W_hh);
    k_init<<<(N_NODES * H + 255) / 256, 256>>>(x, W_in, b_in);

    const int NEL = N_NODES * H;
    const int EDGE_BLOCKS = N_EDGESC / TILE_E + 2;
    for (int l = 0; l < 3; ++l) {
        k_zero_agg<<<(NEL + 255) / 256, 256>>>();
        k_edge_tc<<<EDGE_BLOCKS, 256, EDGE_SMEM>>>(edge_index, b1, b2, l);
        dim3 gg((N_NODES + 127) / 128, 3, 2);
        k_gru_tc<<<gg, 256, GRU_SMEM>>>(b_ih, b_hh, l);
        k_gru_combine<<<(NEL + 255) / 256, 256>>>();
    }

    k_readout<<<625, 256, READ_SMEM>>>(Wr1, br1, Wr2, br2, out, out_size);
}